// round 7
// baseline (speedup 1.0000x reference)
#include <cuda_runtime.h>
#include <cuda_bf16.h>

// ---------------------------------------------------------------------------
// MultiStageDiscriminator — fp32 with packed f32x2 FMA (sm_103a FFMA2).
// ---------------------------------------------------------------------------

#define B_ 16
#define SLOPE 0.2f

// ---- static scratch (zero-initialized; padded borders are never written) ----
__device__ float g_x0p[B_ * 64 * 66 * 66];     // conv0 out, padded 66x66
__device__ float g_x1 [B_ * 128 * 1024];       // post inorm+leaky
__device__ float g_q  [B_ * 16 * 1024];
__device__ float g_k  [B_ * 16 * 1024];
__device__ float g_v  [B_ * 128 * 1024];
__device__ float g_attn[B_ * 1024 * 1024];     // 64 MB
__device__ float g_xap[B_ * 128 * 34 * 34];    // attn residual out, padded 34x34
__device__ float g_x2 [B_ * 256 * 16 * 16];

__device__ __forceinline__ float lrelu(float v) { return v > 0.f ? v : SLOPE * v; }

// ---- packed f32x2 helpers ----
typedef unsigned long long u64;
__device__ __forceinline__ u64 bcast2(float v) {
    u64 r; asm("mov.b64 %0, {%1, %1};" : "=l"(r) : "f"(v)); return r;
}
__device__ __forceinline__ u64 pack2(float lo, float hi) {
    u64 r; asm("mov.b64 %0, {%1, %2};" : "=l"(r) : "f"(lo), "f"(hi)); return r;
}
__device__ __forceinline__ void fma2(u64& acc, u64 a, u64 b) {
    asm("fma.rn.f32x2 %0, %1, %2, %0;" : "+l"(acc) : "l"(a), "l"(b));
}
__device__ __forceinline__ float2 unpk2(u64 v) {
    float2 f; asm("mov.b64 {%0, %1}, %2;" : "=f"(f.x), "=f"(f.y) : "l"(v)); return f;
}

// ---------------------------------------------------------------------------
// K1: conv0 (1->64, k4 s2 p1, 128->64) + leaky -> padded 66x66.
// grid = B*64, block = 256
// ---------------------------------------------------------------------------
__global__ void k_conv0(const float* __restrict__ img, const int* __restrict__ sidx,
                        const float* __restrict__ w0, const float* __restrict__ b0) {
    int b  = blockIdx.x >> 6;
    int oc = blockIdx.x & 63;
    int s  = sidx[b];
    __shared__ float ws[16];
    __shared__ float bias;
    if (threadIdx.x < 16) ws[threadIdx.x] = w0[(s * 64 + oc) * 16 + threadIdx.x];
    if (threadIdx.x == 0) bias = b0[s * 64 + oc];
    __syncthreads();
    const float* im  = img + b * 128 * 128;
    float*       out = g_x0p + (b * 64 + oc) * 4356;
    for (int p = threadIdx.x; p < 4096; p += blockDim.x) {
        int oy = p >> 6, ox = p & 63;
        float acc = bias;
        #pragma unroll
        for (int ky = 0; ky < 4; ky++) {
            int iy = 2 * oy - 1 + ky;
            if ((unsigned)iy < 128u) {
                #pragma unroll
                for (int kx = 0; kx < 4; kx++) {
                    int ix = 2 * ox - 1 + kx;
                    if ((unsigned)ix < 128u)
                        acc += im[iy * 128 + ix] * ws[ky * 4 + kx];
                }
            }
        }
        out[(oy + 1) * 66 + ox + 1] = lrelu(acc);
    }
}

// ---------------------------------------------------------------------------
// K2: conv1 (64->128, k4 s2 p1, 64->32) + FUSED instance-norm + leaky.
// Bias dropped (cancels exactly under instance norm). f32x2 inner loop.
// Block = 1024 (all positions), 8 oc/block, grid = B*16.
// ---------------------------------------------------------------------------
__global__ void __launch_bounds__(1024, 1)
k_conv1(const int* __restrict__ sidx, const float* __restrict__ w1) {
    int b = blockIdx.x >> 4;
    int g = blockIdx.x & 15;
    int s = sidx[b];
    __shared__ __align__(16) float ws[64 * 16 * 8];   // [ic*16+k][8 oc] 32KB
    for (int i = threadIdx.x; i < 8192; i += 1024) {
        int j = i & 7, ick = i >> 3;
        ws[i] = w1[(s * 128 + g * 8 + j) * 1024 + ick];
    }
    __syncthreads();

    int p  = threadIdx.x;
    int oy = p >> 5, ox = p & 31;
    u64 acc2[4] = {0ull, 0ull, 0ull, 0ull};

    const float* xin = g_x0p + b * 64 * 4356 + (2 * oy) * 66 + 2 * ox;
    for (int ic = 0; ic < 64; ic++) {
        const float* xc = xin + ic * 4356;
        const ulonglong2* wrow = (const ulonglong2*)(ws + ic * 128);
        #pragma unroll
        for (int ky = 0; ky < 4; ky++) {
            #pragma unroll
            for (int kx = 0; kx < 4; kx++) {
                u64 v2 = bcast2(xc[ky * 66 + kx]);
                ulonglong2 wa = wrow[(ky * 4 + kx) * 2];
                ulonglong2 wb = wrow[(ky * 4 + kx) * 2 + 1];
                fma2(acc2[0], v2, wa.x); fma2(acc2[1], v2, wa.y);
                fma2(acc2[2], v2, wb.x); fma2(acc2[3], v2, wb.y);
            }
        }
    }
    float acc[8];
    #pragma unroll
    for (int j2 = 0; j2 < 4; j2++) {
        float2 f = unpk2(acc2[j2]);
        acc[2 * j2] = f.x; acc[2 * j2 + 1] = f.y;
    }

    // fused instance norm over the 1024 positions of each of the 8 channels
    __shared__ float wsum[32][8], wsum2[32][8];
    int w = threadIdx.x >> 5, l = threadIdx.x & 31;
    #pragma unroll
    for (int j = 0; j < 8; j++) {
        float sv = acc[j], qv = acc[j] * acc[j];
        #pragma unroll
        for (int o = 16; o; o >>= 1) {
            sv += __shfl_down_sync(~0u, sv, o);
            qv += __shfl_down_sync(~0u, qv, o);
        }
        if (l == 0) { wsum[w][j] = sv; wsum2[w][j] = qv; }
    }
    __syncthreads();
    __shared__ float mean_s[8], inv_s[8];
    if (threadIdx.x < 8) {
        int j = threadIdx.x;
        float sv = 0.f, qv = 0.f;
        #pragma unroll
        for (int ww = 0; ww < 32; ww++) { sv += wsum[ww][j]; qv += wsum2[ww][j]; }
        float m = sv * (1.f / 1024.f);
        float v = qv * (1.f / 1024.f) - m * m;
        mean_s[j] = m;
        inv_s[j]  = rsqrtf(v + 1e-5f);
    }
    __syncthreads();
    float* out = g_x1 + (b * 128 + g * 8) * 1024;
    #pragma unroll
    for (int j = 0; j < 8; j++)
        out[j * 1024 + p] = lrelu((acc[j] - mean_s[j]) * inv_s[j]);
}

// ---------------------------------------------------------------------------
// K3: q/k/v 1x1 convs, f32x2. grid = (4 n-tiles, 10 groups, B), block = 256.
// ---------------------------------------------------------------------------
__global__ void k_qkv(const int* __restrict__ sidx,
                      const float* __restrict__ wq, const float* __restrict__ bq,
                      const float* __restrict__ wk, const float* __restrict__ bk,
                      const float* __restrict__ wv, const float* __restrict__ bv) {
    int b = blockIdx.z;
    int g = blockIdx.y;
    int s = sidx[b];
    const float *W, *Bp;
    float* out;
    if (g == 0)      { W = wq + s * 16 * 128;  Bp = bq + s * 16;  out = g_q + b * 16 * 1024; }
    else if (g == 1) { W = wk + s * 16 * 128;  Bp = bk + s * 16;  out = g_k + b * 16 * 1024; }
    else {
        int ch0 = (g - 2) * 16;
        W   = wv + (s * 128 + ch0) * 128;
        Bp  = bv + s * 128 + ch0;
        out = g_v + (b * 128 + ch0) * 1024;
    }
    __shared__ __align__(16) float ws[128 * 16];   // [c][ch]
    __shared__ float bsm[16];
    for (int i = threadIdx.x; i < 2048; i += blockDim.x) {
        int ch = i & 15, c = i >> 4;
        ws[i] = W[ch * 128 + c];
    }
    if (threadIdx.x < 16) bsm[threadIdx.x] = Bp[threadIdx.x];
    __syncthreads();

    const float* x = g_x1 + b * 128 * 1024;
    int n = blockIdx.x * 256 + threadIdx.x;
    u64 acc2[8];
    #pragma unroll
    for (int j2 = 0; j2 < 8; j2++) acc2[j2] = pack2(bsm[2 * j2], bsm[2 * j2 + 1]);
    for (int c = 0; c < 128; c++) {
        u64 v2 = bcast2(x[c * 1024 + n]);
        const ulonglong2* wr = (const ulonglong2*)(ws + c * 16);
        #pragma unroll
        for (int q4 = 0; q4 < 4; q4++) {
            ulonglong2 w2 = wr[q4];
            fma2(acc2[q4 * 2],     v2, w2.x);
            fma2(acc2[q4 * 2 + 1], v2, w2.y);
        }
    }
    #pragma unroll
    for (int j2 = 0; j2 < 8; j2++) {
        float2 f = unpk2(acc2[j2]);
        out[(2 * j2) * 1024 + n]     = f.x;
        out[(2 * j2 + 1) * 1024 + n] = f.y;
    }
}

// ---------------------------------------------------------------------------
// K4: energies + row softmax. 8 n-rows per 256-thread block. grid = B*128.
// Occupancy fix: unroll-1 m loop + launch_bounds (regs 167 -> <64).
// ---------------------------------------------------------------------------
__global__ void __launch_bounds__(256, 4) k_attn_sm() {
    int b  = blockIdx.x >> 7;
    int n0 = (blockIdx.x & 127) * 8;
    __shared__ float qs[8 * 16];
    __shared__ float es[8 * 1024];   // 32KB
    if (threadIdx.x < 128) {
        int n = threadIdx.x >> 4, i = threadIdx.x & 15;
        qs[n * 16 + i] = g_q[(b * 16 + i) * 1024 + n0 + n];
    }
    __syncthreads();
    const float* kp = g_k + b * 16 * 1024;
    #pragma unroll 1
    for (int m = threadIdx.x; m < 1024; m += 256) {
        float kv[16];
        #pragma unroll
        for (int i = 0; i < 16; i++) kv[i] = kp[i * 1024 + m];
        #pragma unroll
        for (int n = 0; n < 8; n++) {
            float e = 0.f;
            #pragma unroll
            for (int i = 0; i < 16; i++) e += qs[n * 16 + i] * kv[i];
            es[n * 1024 + m] = e;
        }
    }
    __syncthreads();
    int w = threadIdx.x >> 5, l = threadIdx.x & 31;   // warp w owns row w
    float mx = -1e30f;
    for (int m = l; m < 1024; m += 32) mx = fmaxf(mx, es[w * 1024 + m]);
    #pragma unroll
    for (int o = 16; o; o >>= 1) mx = fmaxf(mx, __shfl_xor_sync(~0u, mx, o));
    float sum = 0.f;
    for (int m = l; m < 1024; m += 32) {
        float p = __expf(es[w * 1024 + m] - mx);
        es[w * 1024 + m] = p;
        sum += p;
    }
    #pragma unroll
    for (int o = 16; o; o >>= 1) sum += __shfl_xor_sync(~0u, sum, o);
    float r = 1.f / sum;
    float* out = g_attn + ((size_t)b * 1024 + n0 + w) * 1024;
    for (int m = l; m < 1024; m += 32) out[m] = es[w * 1024 + m] * r;
}

// ---------------------------------------------------------------------------
// K5: xa = gamma * (V @ attn^T) + x1 -> PADDED 34x34.
// 64c x 64n tile, k-chunk 16, 4x4 micro in f32x2. grid = (16, 2, B), block 256.
// ---------------------------------------------------------------------------
__global__ void __launch_bounds__(256, 4)
k_av(const int* __restrict__ sidx, const float* __restrict__ gamma) {
    int b  = blockIdx.z;
    int c0 = blockIdx.y * 64;
    int n0 = blockIdx.x * 64;
    float gm = gamma[sidx[b]];
    const float* V = g_v + b * 128 * 1024;
    const float* P = g_attn + (size_t)b * 1024 * 1024;
    __shared__ __align__(16) float As[16][68];   // V chunk  [m][c]
    __shared__ __align__(16) float Bs[16][68];   // P chunk  [m][n]
    u64 acc2[4][2] = {};
    int tx = threadIdx.x & 15;   // n micro
    int ty = threadIdx.x >> 4;   // c micro / loader column

    for (int m0 = 0; m0 < 1024; m0 += 16) {
        #pragma unroll
        for (int r = 0; r < 4; r++) {
            int cc = ty + r * 16;
            As[tx][cc] = V[(c0 + cc) * 1024 + m0 + tx];
            Bs[tx][cc] = P[(size_t)(n0 + cc) * 1024 + m0 + tx];
        }
        __syncthreads();
        #pragma unroll
        for (int kk = 0; kk < 16; kk++) {
            float4 a = *(const float4*)&As[kk][ty * 4];
            ulonglong2 bb = *(const ulonglong2*)&Bs[kk][tx * 4];
            u64 a0 = bcast2(a.x), a1 = bcast2(a.y), a2 = bcast2(a.z), a3 = bcast2(a.w);
            fma2(acc2[0][0], a0, bb.x); fma2(acc2[0][1], a0, bb.y);
            fma2(acc2[1][0], a1, bb.x); fma2(acc2[1][1], a1, bb.y);
            fma2(acc2[2][0], a2, bb.x); fma2(acc2[2][1], a2, bb.y);
            fma2(acc2[3][0], a3, bb.x); fma2(acc2[3][1], a3, bb.y);
        }
        __syncthreads();
    }

    const float* X = g_x1 + b * 128 * 1024;
    float*       O = g_xap + b * 128 * 1156;
    #pragma unroll
    for (int i = 0; i < 4; i++) {
        int c = c0 + ty * 4 + i;
        float2 lo = unpk2(acc2[i][0]);
        float2 hi = unpk2(acc2[i][1]);
        float vals[4] = {lo.x, lo.y, hi.x, hi.y};
        #pragma unroll
        for (int j = 0; j < 4; j++) {
            int n = n0 + tx * 4 + j;
            int y = n >> 5, x = n & 31;
            O[c * 1156 + (y + 1) * 34 + x + 1] = gm * vals[j] + X[c * 1024 + n];
        }
    }
}

// ---------------------------------------------------------------------------
// K6: conv2 (128->256, k4 s2 p1, 32->16) + FUSED instance-norm + leaky.
// Bias dropped (cancels under inorm). f32x2. grid = B*64, block 256, 4 oc.
// ---------------------------------------------------------------------------
__global__ void k_conv2(const int* __restrict__ sidx, const float* __restrict__ w2) {
    int b = blockIdx.x >> 6;
    int g = blockIdx.x & 63;
    int s = sidx[b];
    __shared__ __align__(16) float ws[128 * 16 * 4];   // [ic*16+k][4 oc] 32KB
    for (int i = threadIdx.x; i < 8192; i += blockDim.x) {
        int j = i & 3;
        int ick = i >> 2;
        ws[i] = w2[(s * 256 + g * 4 + j) * 2048 + ick];
    }
    __syncthreads();

    int oy = threadIdx.x >> 4, ox = threadIdx.x & 15;
    u64 acc2[2] = {0ull, 0ull};
    const float* xin = g_xap + b * 128 * 1156 + (2 * oy) * 34 + 2 * ox;
    for (int ic = 0; ic < 128; ic++) {
        const float* xc = xin + ic * 1156;
        const ulonglong2* wrow = (const ulonglong2*)(ws + ic * 64);
        #pragma unroll
        for (int ky = 0; ky < 4; ky++) {
            #pragma unroll
            for (int kx = 0; kx < 4; kx++) {
                u64 v2 = bcast2(xc[ky * 34 + kx]);
                ulonglong2 w2v = wrow[ky * 4 + kx];
                fma2(acc2[0], v2, w2v.x);
                fma2(acc2[1], v2, w2v.y);
            }
        }
    }
    float acc[4];
    { float2 f = unpk2(acc2[0]); acc[0] = f.x; acc[1] = f.y; }
    { float2 f = unpk2(acc2[1]); acc[2] = f.x; acc[3] = f.y; }

    // fused instance norm over the 256 positions of each of the 4 channels
    __shared__ float wsum[8][4], wsum2[8][4];
    int w = threadIdx.x >> 5, l = threadIdx.x & 31;
    #pragma unroll
    for (int j = 0; j < 4; j++) {
        float sv = acc[j], qv = acc[j] * acc[j];
        #pragma unroll
        for (int o = 16; o; o >>= 1) {
            sv += __shfl_down_sync(~0u, sv, o);
            qv += __shfl_down_sync(~0u, qv, o);
        }
        if (l == 0) { wsum[w][j] = sv; wsum2[w][j] = qv; }
    }
    __syncthreads();
    __shared__ float mean_s[4], inv_s[4];
    if (threadIdx.x < 4) {
        int j = threadIdx.x;
        float sv = 0.f, qv = 0.f;
        #pragma unroll
        for (int ww = 0; ww < 8; ww++) { sv += wsum[ww][j]; qv += wsum2[ww][j]; }
        float m = sv * (1.f / 256.f);
        float v = qv * (1.f / 256.f) - m * m;
        mean_s[j] = m;
        inv_s[j]  = rsqrtf(v + 1e-5f);
    }
    __syncthreads();
    float* out = g_x2 + (b * 256 + g * 4) * 256;
    #pragma unroll
    for (int j = 0; j < 4; j++)
        out[j * 256 + threadIdx.x] = lrelu((acc[j] - mean_s[j]) * inv_s[j]);
}

// ---------------------------------------------------------------------------
// K7: head conv (256->1, k4 s1 p1, 16->15). grid = B, block = 256 (225 used).
// ---------------------------------------------------------------------------
__global__ void k_head(const int* __restrict__ sidx,
                       const float* __restrict__ wh, const float* __restrict__ bh,
                       float* __restrict__ out) {
    int b = blockIdx.x;
    int s = sidx[b];
    __shared__ float ws[256 * 16];   // 16KB
    for (int i = threadIdx.x; i < 4096; i += blockDim.x) ws[i] = wh[s * 4096 + i];
    __shared__ float bias;
    if (threadIdx.x == 0) bias = bh[s];
    __syncthreads();
    if (threadIdx.x < 225) {
        int oy = threadIdx.x / 15, ox = threadIdx.x % 15;
        float acc = bias;
        const float* x = g_x2 + b * 256 * 256;
        for (int ic = 0; ic < 256; ic++) {
            const float* xc = x + ic * 256;
            const float* wr = ws + ic * 16;
            #pragma unroll
            for (int ky = 0; ky < 4; ky++) {
                int iy = oy - 1 + ky;
                if ((unsigned)iy < 16u) {
                    #pragma unroll
                    for (int kx = 0; kx < 4; kx++) {
                        int ix = ox - 1 + kx;
                        if ((unsigned)ix < 16u)
                            acc += xc[iy * 16 + ix] * wr[ky * 4 + kx];
                    }
                }
            }
        }
        out[b * 225 + threadIdx.x] = acc;
    }
}

// ---------------------------------------------------------------------------
extern "C" void kernel_launch(void* const* d_in, const int* in_sizes, int n_in,
                              void* d_out, int out_size) {
    const float* img  = (const float*)d_in[0];
    const int*   sidx = (const int*)  d_in[1];
    const float* w0 = (const float*)d_in[2];
    const float* b0 = (const float*)d_in[3];
    const float* w1 = (const float*)d_in[4];
    const float* w2 = (const float*)d_in[6];
    const float* wq = (const float*)d_in[8];
    const float* bq = (const float*)d_in[9];
    const float* wk = (const float*)d_in[10];
    const float* bk = (const float*)d_in[11];
    const float* wv = (const float*)d_in[12];
    const float* bv = (const float*)d_in[13];
    const float* gamma = (const float*)d_in[14];
    const float* wh = (const float*)d_in[15];
    const float* bh = (const float*)d_in[16];
    float* out = (float*)d_out;

    k_conv0   <<<B_ * 64, 256>>>(img, sidx, w0, b0);
    k_conv1   <<<B_ * 16, 1024>>>(sidx, w1);
    k_qkv     <<<dim3(4, 10, B_), 256>>>(sidx, wq, bq, wk, bk, wv, bv);
    k_attn_sm <<<B_ * 128, 256>>>();
    k_av      <<<dim3(16, 2, B_), 256>>>(sidx, gamma);
    k_conv2   <<<B_ * 64, 256>>>(sidx, w2);
    k_head    <<<B_, 256>>>(sidx, wh, bh, out);
}

// round 8
// speedup vs baseline: 1.0481x; 1.0481x over previous
#include <cuda_runtime.h>
#include <cuda_bf16.h>

// ---------------------------------------------------------------------------
// MultiStageDiscriminator — fp32; f32x2 only in the AV GEMM (high FMA:LDS).
// ---------------------------------------------------------------------------

#define B_ 16
#define SLOPE 0.2f

// ---- static scratch (zero-initialized; padded borders are never written) ----
__device__ float g_x0p[B_ * 64 * 66 * 66];     // conv0 out, padded 66x66
__device__ float g_x1 [B_ * 128 * 1024];       // post inorm+leaky
__device__ float g_q  [B_ * 16 * 1024];
__device__ float g_k  [B_ * 16 * 1024];
__device__ float g_v  [B_ * 128 * 1024];
__device__ float g_attn[B_ * 1024 * 1024];     // 64 MB
__device__ float g_xap[B_ * 128 * 34 * 34];    // attn residual out, padded 34x34
__device__ float g_x2 [B_ * 256 * 16 * 16];

__device__ __forceinline__ float lrelu(float v) { return v > 0.f ? v : SLOPE * v; }

// ---- packed f32x2 helpers (used only in k_av) ----
typedef unsigned long long u64;
__device__ __forceinline__ u64 bcast2(float v) {
    u64 r; asm("mov.b64 %0, {%1, %1};" : "=l"(r) : "f"(v)); return r;
}
__device__ __forceinline__ void fma2(u64& acc, u64 a, u64 b) {
    asm("fma.rn.f32x2 %0, %1, %2, %0;" : "+l"(acc) : "l"(a), "l"(b));
}
__device__ __forceinline__ float2 unpk2(u64 v) {
    float2 f; asm("mov.b64 {%0, %1}, %2;" : "=f"(f.x), "=f"(f.y) : "l"(v)); return f;
}

// ---------------------------------------------------------------------------
// K1: conv0 (1->64, k4 s2 p1, 128->64) + leaky -> padded 66x66.
// grid = B*64, block = 256
// ---------------------------------------------------------------------------
__global__ void k_conv0(const float* __restrict__ img, const int* __restrict__ sidx,
                        const float* __restrict__ w0, const float* __restrict__ b0) {
    int b  = blockIdx.x >> 6;
    int oc = blockIdx.x & 63;
    int s  = sidx[b];
    __shared__ float ws[16];
    __shared__ float bias;
    if (threadIdx.x < 16) ws[threadIdx.x] = w0[(s * 64 + oc) * 16 + threadIdx.x];
    if (threadIdx.x == 0) bias = b0[s * 64 + oc];
    __syncthreads();
    const float* im  = img + b * 128 * 128;
    float*       out = g_x0p + (b * 64 + oc) * 4356;
    for (int p = threadIdx.x; p < 4096; p += blockDim.x) {
        int oy = p >> 6, ox = p & 63;
        float acc = bias;
        #pragma unroll
        for (int ky = 0; ky < 4; ky++) {
            int iy = 2 * oy - 1 + ky;
            if ((unsigned)iy < 128u) {
                #pragma unroll
                for (int kx = 0; kx < 4; kx++) {
                    int ix = 2 * ox - 1 + kx;
                    if ((unsigned)ix < 128u)
                        acc += im[iy * 128 + ix] * ws[ky * 4 + kx];
                }
            }
        }
        out[(oy + 1) * 66 + ox + 1] = lrelu(acc);
    }
}

// ---------------------------------------------------------------------------
// K2: conv1 (64->128, k4 s2 p1, 64->32) + FUSED instance-norm + leaky.
// Bias dropped (cancels exactly under instance norm). Scalar fp32 (LDS-bound).
// Block = 1024 (all positions), 8 oc/block, grid = B*16.
// ---------------------------------------------------------------------------
__global__ void __launch_bounds__(1024, 1)
k_conv1(const int* __restrict__ sidx, const float* __restrict__ w1) {
    int b = blockIdx.x >> 4;
    int g = blockIdx.x & 15;
    int s = sidx[b];
    __shared__ __align__(16) float ws[64 * 16 * 8];   // [ic*16+k][8 oc] 32KB
    for (int i = threadIdx.x; i < 8192; i += 1024) {
        int j = i & 7, ick = i >> 3;
        ws[i] = w1[(s * 128 + g * 8 + j) * 1024 + ick];
    }
    __syncthreads();

    int p  = threadIdx.x;
    int oy = p >> 5, ox = p & 31;
    float acc[8] = {};

    const float* xin = g_x0p + b * 64 * 4356 + (2 * oy) * 66 + 2 * ox;
    for (int ic = 0; ic < 64; ic++) {
        const float* xc   = xin + ic * 4356;
        const float* wrow = ws + ic * 128;
        #pragma unroll
        for (int ky = 0; ky < 4; ky++) {
            #pragma unroll
            for (int kx = 0; kx < 4; kx++) {
                float v = xc[ky * 66 + kx];
                const float* wv = wrow + (ky * 4 + kx) * 8;
                float4 wa = *(const float4*)(wv);
                float4 wb = *(const float4*)(wv + 4);
                acc[0] += v * wa.x; acc[1] += v * wa.y;
                acc[2] += v * wa.z; acc[3] += v * wa.w;
                acc[4] += v * wb.x; acc[5] += v * wb.y;
                acc[6] += v * wb.z; acc[7] += v * wb.w;
            }
        }
    }

    // fused instance norm over the 1024 positions of each of the 8 channels
    __shared__ float wsum[32][8], wsum2[32][8];
    int w = threadIdx.x >> 5, l = threadIdx.x & 31;
    #pragma unroll
    for (int j = 0; j < 8; j++) {
        float sv = acc[j], qv = acc[j] * acc[j];
        #pragma unroll
        for (int o = 16; o; o >>= 1) {
            sv += __shfl_down_sync(~0u, sv, o);
            qv += __shfl_down_sync(~0u, qv, o);
        }
        if (l == 0) { wsum[w][j] = sv; wsum2[w][j] = qv; }
    }
    __syncthreads();
    __shared__ float mean_s[8], inv_s[8];
    if (threadIdx.x < 8) {
        int j = threadIdx.x;
        float sv = 0.f, qv = 0.f;
        #pragma unroll
        for (int ww = 0; ww < 32; ww++) { sv += wsum[ww][j]; qv += wsum2[ww][j]; }
        float m = sv * (1.f / 1024.f);
        float v = qv * (1.f / 1024.f) - m * m;
        mean_s[j] = m;
        inv_s[j]  = rsqrtf(v + 1e-5f);
    }
    __syncthreads();
    float* out = g_x1 + (b * 128 + g * 8) * 1024;
    #pragma unroll
    for (int j = 0; j < 8; j++)
        out[j * 1024 + p] = lrelu((acc[j] - mean_s[j]) * inv_s[j]);
}

// ---------------------------------------------------------------------------
// K3: q/k/v 1x1 convs (scalar). grid = (4 n-tiles, 10 groups, B), block = 256.
// ---------------------------------------------------------------------------
__global__ void k_qkv(const int* __restrict__ sidx,
                      const float* __restrict__ wq, const float* __restrict__ bq,
                      const float* __restrict__ wk, const float* __restrict__ bk,
                      const float* __restrict__ wv, const float* __restrict__ bv) {
    int b = blockIdx.z;
    int g = blockIdx.y;
    int s = sidx[b];
    const float *W, *Bp;
    float* out;
    if (g == 0)      { W = wq + s * 16 * 128;  Bp = bq + s * 16;  out = g_q + b * 16 * 1024; }
    else if (g == 1) { W = wk + s * 16 * 128;  Bp = bk + s * 16;  out = g_k + b * 16 * 1024; }
    else {
        int ch0 = (g - 2) * 16;
        W   = wv + (s * 128 + ch0) * 128;
        Bp  = bv + s * 128 + ch0;
        out = g_v + (b * 128 + ch0) * 1024;
    }
    __shared__ __align__(16) float ws[128 * 16];   // [c][ch]
    __shared__ float bsm[16];
    for (int i = threadIdx.x; i < 2048; i += blockDim.x) {
        int ch = i & 15, c = i >> 4;
        ws[i] = W[ch * 128 + c];
    }
    if (threadIdx.x < 16) bsm[threadIdx.x] = Bp[threadIdx.x];
    __syncthreads();

    const float* x = g_x1 + b * 128 * 1024;
    int n = blockIdx.x * 256 + threadIdx.x;
    float acc[16];
    #pragma unroll
    for (int j = 0; j < 16; j++) acc[j] = bsm[j];
    for (int c = 0; c < 128; c++) {
        float v = x[c * 1024 + n];
        const float* wr = ws + c * 16;
        #pragma unroll
        for (int j = 0; j < 16; j += 4) {
            float4 w4 = *(const float4*)(wr + j);
            acc[j]     += v * w4.x; acc[j + 1] += v * w4.y;
            acc[j + 2] += v * w4.z; acc[j + 3] += v * w4.w;
        }
    }
    #pragma unroll
    for (int j = 0; j < 16; j++) out[j * 1024 + n] = acc[j];
}

// ---------------------------------------------------------------------------
// K4: energies + row softmax — round-6 form (high-MLP, no unroll pragma).
// Block handles (b, 8 rows of n). grid = B*128, block = 256.
// ---------------------------------------------------------------------------
__global__ void k_attn_sm() {
    int b  = blockIdx.x >> 7;
    int n0 = (blockIdx.x & 127) * 8;
    __shared__ float qs[8 * 16];
    __shared__ float es[8 * 1024];   // 32KB
    if (threadIdx.x < 128) {
        int n = threadIdx.x >> 4, i = threadIdx.x & 15;
        qs[n * 16 + i] = g_q[(b * 16 + i) * 1024 + n0 + n];
    }
    __syncthreads();
    const float* kp = g_k + b * 16 * 1024;
    for (int m = threadIdx.x; m < 1024; m += 256) {
        float kv[16];
        #pragma unroll
        for (int i = 0; i < 16; i++) kv[i] = kp[i * 1024 + m];
        #pragma unroll
        for (int n = 0; n < 8; n++) {
            float e = 0.f;
            #pragma unroll
            for (int i = 0; i < 16; i++) e += qs[n * 16 + i] * kv[i];
            es[n * 1024 + m] = e;
        }
    }
    __syncthreads();
    int w = threadIdx.x >> 5, l = threadIdx.x & 31;   // warp w owns row w
    float mx = -1e30f;
    for (int m = l; m < 1024; m += 32) mx = fmaxf(mx, es[w * 1024 + m]);
    #pragma unroll
    for (int o = 16; o; o >>= 1) mx = fmaxf(mx, __shfl_xor_sync(~0u, mx, o));
    float sum = 0.f;
    for (int m = l; m < 1024; m += 32) {
        float p = __expf(es[w * 1024 + m] - mx);
        es[w * 1024 + m] = p;
        sum += p;
    }
    #pragma unroll
    for (int o = 16; o; o >>= 1) sum += __shfl_xor_sync(~0u, sum, o);
    float r = 1.f / sum;
    float* out = g_attn + ((size_t)b * 1024 + n0 + w) * 1024;
    for (int m = l; m < 1024; m += 32) out[m] = es[w * 1024 + m] * r;
}

// ---------------------------------------------------------------------------
// K5: xa = gamma * (V @ attn^T) + x1 -> PADDED 34x34.
// 128c x 128n tile per block, k-chunk 16, 8x8 micro in f32x2.
// grid = (8, B), block = 256 (16x16 threads). One wave of 128 CTAs.
// ---------------------------------------------------------------------------
__global__ void __launch_bounds__(256, 2)
k_av(const int* __restrict__ sidx, const float* __restrict__ gamma) {
    int b  = blockIdx.y;
    int n0 = blockIdx.x * 128;
    float gm = gamma[sidx[b]];
    const float* V = g_v + b * 128 * 1024;
    const float* P = g_attn + (size_t)b * 1024 * 1024;
    __shared__ __align__(16) float As[16][132];   // V chunk  [m][c]  (128 used)
    __shared__ __align__(16) float Bs[16][132];   // P chunk  [m][n]
    u64 acc2[8][4] = {};
    int tx = threadIdx.x & 15;   // n micro (8 cols)
    int ty = threadIdx.x >> 4;   // c micro (8 rows)
    int mm = threadIdx.x & 15;   // loader: m within chunk
    int c0 = threadIdx.x >> 4;   // loader: column base (0..15, step 16)

    for (int m0 = 0; m0 < 1024; m0 += 16) {
        #pragma unroll
        for (int r = 0; r < 8; r++) {
            int cc = c0 + r * 16;
            As[mm][cc] = V[cc * 1024 + m0 + mm];
            Bs[mm][cc] = P[(size_t)(n0 + cc) * 1024 + m0 + mm];
        }
        __syncthreads();
        #pragma unroll
        for (int kk = 0; kk < 16; kk++) {
            float4 a0 = *(const float4*)&As[kk][ty * 8];
            float4 a1 = *(const float4*)&As[kk][ty * 8 + 4];
            ulonglong2 b0 = *(const ulonglong2*)&Bs[kk][tx * 8];
            ulonglong2 b1 = *(const ulonglong2*)&Bs[kk][tx * 8 + 4];
            float av[8] = {a0.x, a0.y, a0.z, a0.w, a1.x, a1.y, a1.z, a1.w};
            #pragma unroll
            for (int i = 0; i < 8; i++) {
                u64 ai = bcast2(av[i]);
                fma2(acc2[i][0], ai, b0.x); fma2(acc2[i][1], ai, b0.y);
                fma2(acc2[i][2], ai, b1.x); fma2(acc2[i][3], ai, b1.y);
            }
        }
        __syncthreads();
    }

    const float* X = g_x1 + b * 128 * 1024;
    float*       O = g_xap + b * 128 * 1156;
    #pragma unroll
    for (int i = 0; i < 8; i++) {
        int c = ty * 8 + i;
        #pragma unroll
        for (int j2 = 0; j2 < 4; j2++) {
            float2 f = unpk2(acc2[i][j2]);
            int n = n0 + tx * 8 + j2 * 2;
            int y0 = n >> 5, x0 = n & 31;          // n and n+1 share row (x0<31)
            O[c * 1156 + (y0 + 1) * 34 + x0 + 1] = gm * f.x + X[c * 1024 + n];
            O[c * 1156 + (y0 + 1) * 34 + x0 + 2] = gm * f.y + X[c * 1024 + n + 1];
        }
    }
}

// ---------------------------------------------------------------------------
// K6: conv2 (128->256, k4 s2 p1, 32->16) + FUSED instance-norm + leaky.
// Bias dropped (cancels under inorm). Scalar fp32. grid = B*64, block 256, 4 oc.
// ---------------------------------------------------------------------------
__global__ void k_conv2(const int* __restrict__ sidx, const float* __restrict__ w2) {
    int b = blockIdx.x >> 6;
    int g = blockIdx.x & 63;
    int s = sidx[b];
    __shared__ __align__(16) float ws[128 * 16 * 4];   // [ic*16+k][4 oc] 32KB
    for (int i = threadIdx.x; i < 8192; i += blockDim.x) {
        int j = i & 3;
        int ick = i >> 2;
        ws[i] = w2[(s * 256 + g * 4 + j) * 2048 + ick];
    }
    __syncthreads();

    int oy = threadIdx.x >> 4, ox = threadIdx.x & 15;
    float acc[4] = {};
    const float* xin = g_xap + b * 128 * 1156 + (2 * oy) * 34 + 2 * ox;
    for (int ic = 0; ic < 128; ic++) {
        const float* xc = xin + ic * 1156;
        const float* wr = ws + ic * 64;
        #pragma unroll
        for (int ky = 0; ky < 4; ky++) {
            #pragma unroll
            for (int kx = 0; kx < 4; kx++) {
                float v = xc[ky * 34 + kx];
                float4 w4 = *(const float4*)(wr + (ky * 4 + kx) * 4);
                acc[0] += v * w4.x; acc[1] += v * w4.y;
                acc[2] += v * w4.z; acc[3] += v * w4.w;
            }
        }
    }

    // fused instance norm over the 256 positions of each of the 4 channels
    __shared__ float wsum[8][4], wsum2[8][4];
    int w = threadIdx.x >> 5, l = threadIdx.x & 31;
    #pragma unroll
    for (int j = 0; j < 4; j++) {
        float sv = acc[j], qv = acc[j] * acc[j];
        #pragma unroll
        for (int o = 16; o; o >>= 1) {
            sv += __shfl_down_sync(~0u, sv, o);
            qv += __shfl_down_sync(~0u, qv, o);
        }
        if (l == 0) { wsum[w][j] = sv; wsum2[w][j] = qv; }
    }
    __syncthreads();
    __shared__ float mean_s[4], inv_s[4];
    if (threadIdx.x < 4) {
        int j = threadIdx.x;
        float sv = 0.f, qv = 0.f;
        #pragma unroll
        for (int ww = 0; ww < 8; ww++) { sv += wsum[ww][j]; qv += wsum2[ww][j]; }
        float m = sv * (1.f / 256.f);
        float v = qv * (1.f / 256.f) - m * m;
        mean_s[j] = m;
        inv_s[j]  = rsqrtf(v + 1e-5f);
    }
    __syncthreads();
    float* out = g_x2 + (b * 256 + g * 4) * 256;
    #pragma unroll
    for (int j = 0; j < 4; j++)
        out[j * 256 + threadIdx.x] = lrelu((acc[j] - mean_s[j]) * inv_s[j]);
}

// ---------------------------------------------------------------------------
// K7: head conv (256->1, k4 s1 p1, 16->15). grid = B, block = 256 (225 used).
// ---------------------------------------------------------------------------
__global__ void k_head(const int* __restrict__ sidx,
                       const float* __restrict__ wh, const float* __restrict__ bh,
                       float* __restrict__ out) {
    int b = blockIdx.x;
    int s = sidx[b];
    __shared__ float ws[256 * 16];   // 16KB
    for (int i = threadIdx.x; i < 4096; i += blockDim.x) ws[i] = wh[s * 4096 + i];
    __shared__ float bias;
    if (threadIdx.x == 0) bias = bh[s];
    __syncthreads();
    if (threadIdx.x < 225) {
        int oy = threadIdx.x / 15, ox = threadIdx.x % 15;
        float acc = bias;
        const float* x = g_x2 + b * 256 * 256;
        for (int ic = 0; ic < 256; ic++) {
            const float* xc = x + ic * 256;
            const float* wr = ws + ic * 16;
            #pragma unroll
            for (int ky = 0; ky < 4; ky++) {
                int iy = oy - 1 + ky;
                if ((unsigned)iy < 16u) {
                    #pragma unroll
                    for (int kx = 0; kx < 4; kx++) {
                        int ix = ox - 1 + kx;
                        if ((unsigned)ix < 16u)
                            acc += xc[iy * 16 + ix] * wr[ky * 4 + kx];
                    }
                }
            }
        }
        out[b * 225 + threadIdx.x] = acc;
    }
}

// ---------------------------------------------------------------------------
extern "C" void kernel_launch(void* const* d_in, const int* in_sizes, int n_in,
                              void* d_out, int out_size) {
    const float* img  = (const float*)d_in[0];
    const int*   sidx = (const int*)  d_in[1];
    const float* w0 = (const float*)d_in[2];
    const float* b0 = (const float*)d_in[3];
    const float* w1 = (const float*)d_in[4];
    const float* w2 = (const float*)d_in[6];
    const float* wq = (const float*)d_in[8];
    const float* bq = (const float*)d_in[9];
    const float* wk = (const float*)d_in[10];
    const float* bk = (const float*)d_in[11];
    const float* wv = (const float*)d_in[12];
    const float* bv = (const float*)d_in[13];
    const float* gamma = (const float*)d_in[14];
    const float* wh = (const float*)d_in[15];
    const float* bh = (const float*)d_in[16];
    float* out = (float*)d_out;

    k_conv0   <<<B_ * 64, 256>>>(img, sidx, w0, b0);
    k_conv1   <<<B_ * 16, 1024>>>(sidx, w1);
    k_qkv     <<<dim3(4, 10, B_), 256>>>(sidx, wq, bq, wk, bk, wv, bv);
    k_attn_sm <<<B_ * 128, 256>>>();
    k_av      <<<dim3(8, B_), 256>>>(sidx, gamma);
    k_conv2   <<<B_ * 64, 256>>>(sidx, w2);
    k_head    <<<B_, 256>>>(sidx, wh, bh, out);
}

// round 9
// speedup vs baseline: 1.1568x; 1.1037x over previous
#include <cuda_runtime.h>
#include <cuda_bf16.h>
#include <cstdint>

// ---------------------------------------------------------------------------
// MultiStageDiscriminator — fp32 convs; tf32 mma.sync for the AV GEMM.
// ---------------------------------------------------------------------------

#define B_ 16
#define SLOPE 0.2f

// ---- static scratch (zero-initialized; padded borders are never written) ----
__device__ float g_x0p[B_ * 64 * 66 * 66];     // conv0 out, padded 66x66
__device__ float g_x1 [B_ * 128 * 1024];       // post inorm+leaky
__device__ float g_q  [B_ * 16 * 1024];
__device__ float g_k  [B_ * 16 * 1024];
__device__ float g_v  [B_ * 128 * 1024];
__device__ float g_attn[B_ * 1024 * 1024];     // 64 MB
__device__ float g_xap[B_ * 128 * 34 * 34];    // attn residual out, padded 34x34
__device__ float g_x2 [B_ * 256 * 16 * 16];

__device__ __forceinline__ float lrelu(float v) { return v > 0.f ? v : SLOPE * v; }

// round fp32 -> tf32 (rna), result kept in an f32 register (bit pattern)
__device__ __forceinline__ float tf32r(float x) {
    float r; asm("cvt.rna.tf32.f32 %0, %1;" : "=f"(r) : "f"(x)); return r;
}

__device__ __forceinline__ void mma_tf32(float d[4],
                                         uint32_t a0, uint32_t a1, uint32_t a2, uint32_t a3,
                                         uint32_t b0, uint32_t b1) {
    asm volatile(
        "mma.sync.aligned.m16n8k8.row.col.f32.tf32.tf32.f32 "
        "{%0,%1,%2,%3}, {%4,%5,%6,%7}, {%8,%9}, {%0,%1,%2,%3};\n"
        : "+f"(d[0]), "+f"(d[1]), "+f"(d[2]), "+f"(d[3])
        : "r"(a0), "r"(a1), "r"(a2), "r"(a3), "r"(b0), "r"(b1));
}

// ---------------------------------------------------------------------------
// K1: conv0 (1->64, k4 s2 p1, 128->64) + leaky -> padded 66x66.
// grid = B*64, block = 256
// ---------------------------------------------------------------------------
__global__ void k_conv0(const float* __restrict__ img, const int* __restrict__ sidx,
                        const float* __restrict__ w0, const float* __restrict__ b0) {
    int b  = blockIdx.x >> 6;
    int oc = blockIdx.x & 63;
    int s  = sidx[b];
    __shared__ float ws[16];
    __shared__ float bias;
    if (threadIdx.x < 16) ws[threadIdx.x] = w0[(s * 64 + oc) * 16 + threadIdx.x];
    if (threadIdx.x == 0) bias = b0[s * 64 + oc];
    __syncthreads();
    const float* im  = img + b * 128 * 128;
    float*       out = g_x0p + (b * 64 + oc) * 4356;
    for (int p = threadIdx.x; p < 4096; p += blockDim.x) {
        int oy = p >> 6, ox = p & 63;
        float acc = bias;
        #pragma unroll
        for (int ky = 0; ky < 4; ky++) {
            int iy = 2 * oy - 1 + ky;
            if ((unsigned)iy < 128u) {
                #pragma unroll
                for (int kx = 0; kx < 4; kx++) {
                    int ix = 2 * ox - 1 + kx;
                    if ((unsigned)ix < 128u)
                        acc += im[iy * 128 + ix] * ws[ky * 4 + kx];
                }
            }
        }
        out[(oy + 1) * 66 + ox + 1] = lrelu(acc);
    }
}

// ---------------------------------------------------------------------------
// K2: conv1 (64->128, k4 s2 p1, 64->32) + FUSED instance-norm + leaky.
// Bias dropped (cancels exactly under instance norm). Scalar fp32.
// Block = 1024 (all positions), 8 oc/block, grid = B*16.
// ---------------------------------------------------------------------------
__global__ void __launch_bounds__(1024, 1)
k_conv1(const int* __restrict__ sidx, const float* __restrict__ w1) {
    int b = blockIdx.x >> 4;
    int g = blockIdx.x & 15;
    int s = sidx[b];
    __shared__ __align__(16) float ws[64 * 16 * 8];   // [ic*16+k][8 oc] 32KB
    for (int i = threadIdx.x; i < 8192; i += 1024) {
        int j = i & 7, ick = i >> 3;
        ws[i] = w1[(s * 128 + g * 8 + j) * 1024 + ick];
    }
    __syncthreads();

    int p  = threadIdx.x;
    int oy = p >> 5, ox = p & 31;
    float acc[8] = {};

    const float* xin = g_x0p + b * 64 * 4356 + (2 * oy) * 66 + 2 * ox;
    for (int ic = 0; ic < 64; ic++) {
        const float* xc   = xin + ic * 4356;
        const float* wrow = ws + ic * 128;
        #pragma unroll
        for (int ky = 0; ky < 4; ky++) {
            #pragma unroll
            for (int kx = 0; kx < 4; kx++) {
                float v = xc[ky * 66 + kx];
                const float* wv = wrow + (ky * 4 + kx) * 8;
                float4 wa = *(const float4*)(wv);
                float4 wb = *(const float4*)(wv + 4);
                acc[0] += v * wa.x; acc[1] += v * wa.y;
                acc[2] += v * wa.z; acc[3] += v * wa.w;
                acc[4] += v * wb.x; acc[5] += v * wb.y;
                acc[6] += v * wb.z; acc[7] += v * wb.w;
            }
        }
    }

    __shared__ float wsum[32][8], wsum2[32][8];
    int w = threadIdx.x >> 5, l = threadIdx.x & 31;
    #pragma unroll
    for (int j = 0; j < 8; j++) {
        float sv = acc[j], qv = acc[j] * acc[j];
        #pragma unroll
        for (int o = 16; o; o >>= 1) {
            sv += __shfl_down_sync(~0u, sv, o);
            qv += __shfl_down_sync(~0u, qv, o);
        }
        if (l == 0) { wsum[w][j] = sv; wsum2[w][j] = qv; }
    }
    __syncthreads();
    __shared__ float mean_s[8], inv_s[8];
    if (threadIdx.x < 8) {
        int j = threadIdx.x;
        float sv = 0.f, qv = 0.f;
        #pragma unroll
        for (int ww = 0; ww < 32; ww++) { sv += wsum[ww][j]; qv += wsum2[ww][j]; }
        float m = sv * (1.f / 1024.f);
        float v = qv * (1.f / 1024.f) - m * m;
        mean_s[j] = m;
        inv_s[j]  = rsqrtf(v + 1e-5f);
    }
    __syncthreads();
    float* out = g_x1 + (b * 128 + g * 8) * 1024;
    #pragma unroll
    for (int j = 0; j < 8; j++)
        out[j * 1024 + p] = lrelu((acc[j] - mean_s[j]) * inv_s[j]);
}

// ---------------------------------------------------------------------------
// K3: q/k/v 1x1 convs (scalar). grid = (4 n-tiles, 10 groups, B), block = 256.
// ---------------------------------------------------------------------------
__global__ void k_qkv(const int* __restrict__ sidx,
                      const float* __restrict__ wq, const float* __restrict__ bq,
                      const float* __restrict__ wk, const float* __restrict__ bk,
                      const float* __restrict__ wv, const float* __restrict__ bv) {
    int b = blockIdx.z;
    int g = blockIdx.y;
    int s = sidx[b];
    const float *W, *Bp;
    float* out;
    if (g == 0)      { W = wq + s * 16 * 128;  Bp = bq + s * 16;  out = g_q + b * 16 * 1024; }
    else if (g == 1) { W = wk + s * 16 * 128;  Bp = bk + s * 16;  out = g_k + b * 16 * 1024; }
    else {
        int ch0 = (g - 2) * 16;
        W   = wv + (s * 128 + ch0) * 128;
        Bp  = bv + s * 128 + ch0;
        out = g_v + (b * 128 + ch0) * 1024;
    }
    __shared__ __align__(16) float ws[128 * 16];   // [c][ch]
    __shared__ float bsm[16];
    for (int i = threadIdx.x; i < 2048; i += blockDim.x) {
        int ch = i & 15, c = i >> 4;
        ws[i] = W[ch * 128 + c];
    }
    if (threadIdx.x < 16) bsm[threadIdx.x] = Bp[threadIdx.x];
    __syncthreads();

    const float* x = g_x1 + b * 128 * 1024;
    int n = blockIdx.x * 256 + threadIdx.x;
    float acc[16];
    #pragma unroll
    for (int j = 0; j < 16; j++) acc[j] = bsm[j];
    for (int c = 0; c < 128; c++) {
        float v = x[c * 1024 + n];
        const float* wr = ws + c * 16;
        #pragma unroll
        for (int j = 0; j < 16; j += 4) {
            float4 w4 = *(const float4*)(wr + j);
            acc[j]     += v * w4.x; acc[j + 1] += v * w4.y;
            acc[j + 2] += v * w4.z; acc[j + 3] += v * w4.w;
        }
    }
    #pragma unroll
    for (int j = 0; j < 16; j++) out[j * 1024 + n] = acc[j];
}

// ---------------------------------------------------------------------------
// K4: energies + row softmax — high-MLP form (best measured: 63 us).
// Block handles (b, 8 rows of n). grid = B*128, block = 256.
// ---------------------------------------------------------------------------
__global__ void k_attn_sm() {
    int b  = blockIdx.x >> 7;
    int n0 = (blockIdx.x & 127) * 8;
    __shared__ float qs[8 * 16];
    __shared__ float es[8 * 1024];   // 32KB
    if (threadIdx.x < 128) {
        int n = threadIdx.x >> 4, i = threadIdx.x & 15;
        qs[n * 16 + i] = g_q[(b * 16 + i) * 1024 + n0 + n];
    }
    __syncthreads();
    const float* kp = g_k + b * 16 * 1024;
    for (int m = threadIdx.x; m < 1024; m += 256) {
        float kv[16];
        #pragma unroll
        for (int i = 0; i < 16; i++) kv[i] = kp[i * 1024 + m];
        #pragma unroll
        for (int n = 0; n < 8; n++) {
            float e = 0.f;
            #pragma unroll
            for (int i = 0; i < 16; i++) e += qs[n * 16 + i] * kv[i];
            es[n * 1024 + m] = e;
        }
    }
    __syncthreads();
    int w = threadIdx.x >> 5, l = threadIdx.x & 31;   // warp w owns row w
    float mx = -1e30f;
    for (int m = l; m < 1024; m += 32) mx = fmaxf(mx, es[w * 1024 + m]);
    #pragma unroll
    for (int o = 16; o; o >>= 1) mx = fmaxf(mx, __shfl_xor_sync(~0u, mx, o));
    float sum = 0.f;
    for (int m = l; m < 1024; m += 32) {
        float p = __expf(es[w * 1024 + m] - mx);
        es[w * 1024 + m] = p;
        sum += p;
    }
    #pragma unroll
    for (int o = 16; o; o >>= 1) sum += __shfl_xor_sync(~0u, sum, o);
    float r = 1.f / sum;
    float* out = g_attn + ((size_t)b * 1024 + n0 + w) * 1024;
    for (int m = l; m < 1024; m += 32) out[m] = es[w * 1024 + m] * r;
}

// ---------------------------------------------------------------------------
// K5: xa = gamma * (V @ attn^T) + x1 -> PADDED 34x34.   [tf32 mma.sync]
// C[c][n] = sum_m V[c][m] * P[n][m]  (row.col: both contiguous in m=k)
// Block 256 (8 warps): tile M=128(c) x N=64(n), K-chunk 32.
// Warp grid 4(m) x 2(n): each warp 32x32 via m16n8k8 frags (2 m x 4 n).
// grid = (16 n-tiles, B). smem 27KB -> 2 CTAs/SM.
// ---------------------------------------------------------------------------
__global__ void __launch_bounds__(256, 2)
k_av(const int* __restrict__ sidx, const float* __restrict__ gamma) {
    int b  = blockIdx.y;
    int n0 = blockIdx.x * 64;
    float gm = gamma[sidx[b]];
    const float* V = g_v + b * 128 * 1024;
    const float* P = g_attn + (size_t)b * 1024 * 1024;

    __shared__ __align__(16) float As[128][36];   // [c][k]  18KB (rows 144B)
    __shared__ __align__(16) float Bs[64][36];    // [n][k]   9KB

    int tid  = threadIdx.x;
    int wid  = tid >> 5, lane = tid & 31;
    int warp_m = wid & 3;          // 0..3 -> c block of 32
    int warp_n = wid >> 2;         // 0..1 -> n block of 32
    int cw = warp_m * 32;
    int nw = warp_n * 32;
    int gr = lane >> 2;            // 0..7
    int tg = lane & 3;             // 0..3

    float acc[2][4][4];
    #pragma unroll
    for (int mi = 0; mi < 2; mi++)
        #pragma unroll
        for (int nj = 0; nj < 4; nj++)
            #pragma unroll
            for (int r = 0; r < 4; r++) acc[mi][nj][r] = 0.f;

    for (int m0 = 0; m0 < 1024; m0 += 32) {
        // stage A: 128 x 32 (1024 float4, 4/thread)
        #pragma unroll
        for (int r = 0; r < 4; r++) {
            int idx = tid + r * 256;
            int c   = idx >> 3;
            int k4  = (idx & 7) * 4;
            float4 v = *(const float4*)&V[c * 1024 + m0 + k4];
            As[c][k4 + 0] = tf32r(v.x);
            As[c][k4 + 1] = tf32r(v.y);
            As[c][k4 + 2] = tf32r(v.z);
            As[c][k4 + 3] = tf32r(v.w);
        }
        // stage B: 64 x 32 (512 float4, 2/thread)
        #pragma unroll
        for (int r = 0; r < 2; r++) {
            int idx = tid + r * 256;
            int n   = idx >> 3;
            int k4  = (idx & 7) * 4;
            float4 v = *(const float4*)&P[(size_t)(n0 + n) * 1024 + m0 + k4];
            Bs[n][k4 + 0] = tf32r(v.x);
            Bs[n][k4 + 1] = tf32r(v.y);
            Bs[n][k4 + 2] = tf32r(v.z);
            Bs[n][k4 + 3] = tf32r(v.w);
        }
        __syncthreads();

        #pragma unroll
        for (int k8 = 0; k8 < 32; k8 += 8) {
            uint32_t a[2][4];
            #pragma unroll
            for (int mi = 0; mi < 2; mi++) {
                a[mi][0] = __float_as_uint(As[cw + mi * 16 + gr    ][k8 + tg    ]);
                a[mi][1] = __float_as_uint(As[cw + mi * 16 + gr + 8][k8 + tg    ]);
                a[mi][2] = __float_as_uint(As[cw + mi * 16 + gr    ][k8 + tg + 4]);
                a[mi][3] = __float_as_uint(As[cw + mi * 16 + gr + 8][k8 + tg + 4]);
            }
            uint32_t bf[4][2];
            #pragma unroll
            for (int nj = 0; nj < 4; nj++) {
                bf[nj][0] = __float_as_uint(Bs[nw + nj * 8 + gr][k8 + tg    ]);
                bf[nj][1] = __float_as_uint(Bs[nw + nj * 8 + gr][k8 + tg + 4]);
            }
            #pragma unroll
            for (int mi = 0; mi < 2; mi++)
                #pragma unroll
                for (int nj = 0; nj < 4; nj++)
                    mma_tf32(acc[mi][nj], a[mi][0], a[mi][1], a[mi][2], a[mi][3],
                             bf[nj][0], bf[nj][1]);
        }
        __syncthreads();
    }

    // epilogue: residual + gamma, padded 34x34 store
    const float* X = g_x1 + b * 128 * 1024;
    float*       O = g_xap + b * 128 * 1156;
    #pragma unroll
    for (int mi = 0; mi < 2; mi++) {
        int c_lo = cw + mi * 16 + gr;
        int c_hi = c_lo + 8;
        #pragma unroll
        for (int nj = 0; nj < 4; nj++) {
            int n = n0 + nw + nj * 8 + tg * 2;
            int y = n >> 5, x = n & 31;          // n, n+1 share the row (x even)
            int po = (y + 1) * 34 + x + 1;
            O[c_lo * 1156 + po]     = gm * acc[mi][nj][0] + X[c_lo * 1024 + n];
            O[c_lo * 1156 + po + 1] = gm * acc[mi][nj][1] + X[c_lo * 1024 + n + 1];
            O[c_hi * 1156 + po]     = gm * acc[mi][nj][2] + X[c_hi * 1024 + n];
            O[c_hi * 1156 + po + 1] = gm * acc[mi][nj][3] + X[c_hi * 1024 + n + 1];
        }
    }
}

// ---------------------------------------------------------------------------
// K6: conv2 (128->256, k4 s2 p1, 32->16) + FUSED instance-norm + leaky.
// Bias dropped (cancels under inorm). Scalar fp32. grid = B*64, block 256, 4 oc.
// ---------------------------------------------------------------------------
__global__ void k_conv2(const int* __restrict__ sidx, const float* __restrict__ w2) {
    int b = blockIdx.x >> 6;
    int g = blockIdx.x & 63;
    int s = sidx[b];
    __shared__ __align__(16) float ws[128 * 16 * 4];   // [ic*16+k][4 oc] 32KB
    for (int i = threadIdx.x; i < 8192; i += blockDim.x) {
        int j = i & 3;
        int ick = i >> 2;
        ws[i] = w2[(s * 256 + g * 4 + j) * 2048 + ick];
    }
    __syncthreads();

    int oy = threadIdx.x >> 4, ox = threadIdx.x & 15;
    float acc[4] = {};
    const float* xin = g_xap + b * 128 * 1156 + (2 * oy) * 34 + 2 * ox;
    for (int ic = 0; ic < 128; ic++) {
        const float* xc = xin + ic * 1156;
        const float* wr = ws + ic * 64;
        #pragma unroll
        for (int ky = 0; ky < 4; ky++) {
            #pragma unroll
            for (int kx = 0; kx < 4; kx++) {
                float v = xc[ky * 34 + kx];
                float4 w4 = *(const float4*)(wr + (ky * 4 + kx) * 4);
                acc[0] += v * w4.x; acc[1] += v * w4.y;
                acc[2] += v * w4.z; acc[3] += v * w4.w;
            }
        }
    }

    __shared__ float wsum[8][4], wsum2[8][4];
    int w = threadIdx.x >> 5, l = threadIdx.x & 31;
    #pragma unroll
    for (int j = 0; j < 4; j++) {
        float sv = acc[j], qv = acc[j] * acc[j];
        #pragma unroll
        for (int o = 16; o; o >>= 1) {
            sv += __shfl_down_sync(~0u, sv, o);
            qv += __shfl_down_sync(~0u, qv, o);
        }
        if (l == 0) { wsum[w][j] = sv; wsum2[w][j] = qv; }
    }
    __syncthreads();
    __shared__ float mean_s[4], inv_s[4];
    if (threadIdx.x < 4) {
        int j = threadIdx.x;
        float sv = 0.f, qv = 0.f;
        #pragma unroll
        for (int ww = 0; ww < 8; ww++) { sv += wsum[ww][j]; qv += wsum2[ww][j]; }
        float m = sv * (1.f / 256.f);
        float v = qv * (1.f / 256.f) - m * m;
        mean_s[j] = m;
        inv_s[j]  = rsqrtf(v + 1e-5f);
    }
    __syncthreads();
    float* out = g_x2 + (b * 256 + g * 4) * 256;
    #pragma unroll
    for (int j = 0; j < 4; j++)
        out[j * 256 + threadIdx.x] = lrelu((acc[j] - mean_s[j]) * inv_s[j]);
}

// ---------------------------------------------------------------------------
// K7: head conv (256->1, k4 s1 p1, 16->15). grid = B, block = 256 (225 used).
// ---------------------------------------------------------------------------
__global__ void k_head(const int* __restrict__ sidx,
                       const float* __restrict__ wh, const float* __restrict__ bh,
                       float* __restrict__ out) {
    int b = blockIdx.x;
    int s = sidx[b];
    __shared__ float ws[256 * 16];   // 16KB
    for (int i = threadIdx.x; i < 4096; i += blockDim.x) ws[i] = wh[s * 4096 + i];
    __shared__ float bias;
    if (threadIdx.x == 0) bias = bh[s];
    __syncthreads();
    if (threadIdx.x < 225) {
        int oy = threadIdx.x / 15, ox = threadIdx.x % 15;
        float acc = bias;
        const float* x = g_x2 + b * 256 * 256;
        for (int ic = 0; ic < 256; ic++) {
            const float* xc = x + ic * 256;
            const float* wr = ws + ic * 16;
            #pragma unroll
            for (int ky = 0; ky < 4; ky++) {
                int iy = oy - 1 + ky;
                if ((unsigned)iy < 16u) {
                    #pragma unroll
                    for (int kx = 0; kx < 4; kx++) {
                        int ix = ox - 1 + kx;
                        if ((unsigned)ix < 16u)
                            acc += xc[iy * 16 + ix] * wr[ky * 4 + kx];
                    }
                }
            }
        }
        out[b * 225 + threadIdx.x] = acc;
    }
}

// ---------------------------------------------------------------------------
extern "C" void kernel_launch(void* const* d_in, const int* in_sizes, int n_in,
                              void* d_out, int out_size) {
    const float* img  = (const float*)d_in[0];
    const int*   sidx = (const int*)  d_in[1];
    const float* w0 = (const float*)d_in[2];
    const float* b0 = (const float*)d_in[3];
    const float* w1 = (const float*)d_in[4];
    const float* w2 = (const float*)d_in[6];
    const float* wq = (const float*)d_in[8];
    const float* bq = (const float*)d_in[9];
    const float* wk = (const float*)d_in[10];
    const float* bk = (const float*)d_in[11];
    const float* wv = (const float*)d_in[12];
    const float* bv = (const float*)d_in[13];
    const float* gamma = (const float*)d_in[14];
    const float* wh = (const float*)d_in[15];
    const float* bh = (const float*)d_in[16];
    float* out = (float*)d_out;

    k_conv0   <<<B_ * 64, 256>>>(img, sidx, w0, b0);
    k_conv1   <<<B_ * 16, 1024>>>(sidx, w1);
    k_qkv     <<<dim3(4, 10, B_), 256>>>(sidx, wq, bq, wk, bk, wv, bv);
    k_attn_sm <<<B_ * 128, 256>>>();
    k_av      <<<dim3(16, B_), 256>>>(sidx, gamma);
    k_conv2   <<<B_ * 64, 256>>>(sidx, w2);
    k_head    <<<B_, 256>>>(sidx, wh, bh, out);
}

// round 10
// speedup vs baseline: 2.0514x; 1.7733x over previous
#include <cuda_runtime.h>
#include <cuda_bf16.h>
#include <cstdint>

// ---------------------------------------------------------------------------
// MultiStageDiscriminator — tf32 mma for conv1/conv2/AV; scalar elsewhere.
// ---------------------------------------------------------------------------

#define B_ 16
#define SLOPE 0.2f

// ---- static scratch (zero-initialized; padded borders are never written) ----
__device__ float g_x0p[B_ * 64 * 66 * 66];     // conv0 out, padded 66x66
__device__ float g_t1 [B_ * 128 * 1024];       // conv1 raw (pre-norm)
__device__ float g_x1 [B_ * 128 * 1024];       // post inorm+leaky
__device__ float g_q  [B_ * 16 * 1024];
__device__ float g_k  [B_ * 16 * 1024];
__device__ float g_v  [B_ * 128 * 1024];
__device__ float g_attn[B_ * 1024 * 1024];     // 64 MB
__device__ float g_xap[B_ * 128 * 34 * 34];    // attn residual out, padded 34x34
__device__ float g_t2p[4 * B_ * 256 * 256];    // conv2 K-split partials (67MB)
__device__ float g_x2 [B_ * 256 * 16 * 16];

__device__ __forceinline__ float lrelu(float v) { return v > 0.f ? v : SLOPE * v; }

// round fp32 -> tf32 (rna), bit pattern kept in f32 register
__device__ __forceinline__ float tf32r(float x) {
    float r; asm("cvt.rna.tf32.f32 %0, %1;" : "=f"(r) : "f"(x)); return r;
}

__device__ __forceinline__ void mma_tf32(float d[4],
                                         uint32_t a0, uint32_t a1, uint32_t a2, uint32_t a3,
                                         uint32_t b0, uint32_t b1) {
    asm volatile(
        "mma.sync.aligned.m16n8k8.row.col.f32.tf32.tf32.f32 "
        "{%0,%1,%2,%3}, {%4,%5,%6,%7}, {%8,%9}, {%0,%1,%2,%3};\n"
        : "+f"(d[0]), "+f"(d[1]), "+f"(d[2]), "+f"(d[3])
        : "r"(a0), "r"(a1), "r"(a2), "r"(a3), "r"(b0), "r"(b1));
}

// ---------------------------------------------------------------------------
// K1: conv0 (1->64, k4 s2 p1, 128->64) + leaky -> padded 66x66.
// ---------------------------------------------------------------------------
__global__ void k_conv0(const float* __restrict__ img, const int* __restrict__ sidx,
                        const float* __restrict__ w0, const float* __restrict__ b0) {
    int b  = blockIdx.x >> 6;
    int oc = blockIdx.x & 63;
    int s  = sidx[b];
    __shared__ float ws[16];
    __shared__ float bias;
    if (threadIdx.x < 16) ws[threadIdx.x] = w0[(s * 64 + oc) * 16 + threadIdx.x];
    if (threadIdx.x == 0) bias = b0[s * 64 + oc];
    __syncthreads();
    const float* im  = img + b * 128 * 128;
    float*       out = g_x0p + (b * 64 + oc) * 4356;
    for (int p = threadIdx.x; p < 4096; p += blockDim.x) {
        int oy = p >> 6, ox = p & 63;
        float acc = bias;
        #pragma unroll
        for (int ky = 0; ky < 4; ky++) {
            int iy = 2 * oy - 1 + ky;
            if ((unsigned)iy < 128u) {
                #pragma unroll
                for (int kx = 0; kx < 4; kx++) {
                    int ix = 2 * ox - 1 + kx;
                    if ((unsigned)ix < 128u)
                        acc += im[iy * 128 + ix] * ws[ky * 4 + kx];
                }
            }
        }
        out[(oy + 1) * 66 + ox + 1] = lrelu(acc);
    }
}

// ---------------------------------------------------------------------------
// K2: conv1 as tf32 implicit GEMM. C[128oc x 128n] per CTA; K=1024 (64ic x 16),
// K-chunk 32 (2 ic). Bias dropped (cancels under inorm). Raw out -> g_t1.
// grid = (8 n-tiles, B), block = 256 (8 warps, 2m x 4n).
// ---------------------------------------------------------------------------
__global__ void __launch_bounds__(256, 2)
k_conv1g(const int* __restrict__ sidx, const float* __restrict__ w1) {
    int b  = blockIdx.y;
    int n0 = blockIdx.x * 128;
    int s  = sidx[b];
    __shared__ __align__(16) float As[128][36];   // weights [oc][k]   18KB
    __shared__ __align__(16) float Bs[32][136];   // patches [k][n]    17.4KB

    int tid  = threadIdx.x;
    int wid  = tid >> 5, lane = tid & 31;
    int warp_m = wid >> 2;        // 0..1
    int warp_n = wid & 3;         // 0..3
    int cw = warp_m * 64;
    int nw = warp_n * 32;
    int gr = lane >> 2, tg = lane & 3;

    float acc[4][4][4] = {};

    // gather coords (fixed per thread)
    int nn = tid & 127, kh = tid >> 7;     // kh: which of the 2 ic in the chunk
    int n  = n0 + nn;
    int oy = n >> 5, ox = n & 31;
    const float* wbase = w1 + (size_t)(s * 128) * 1024;
    int a_oc = tid >> 1, a_k0 = (tid & 1) * 16;

    for (int m0 = 0; m0 < 1024; m0 += 32) {
        // stage A (weights 128x32, coalesced)
        {
            const float* wr = wbase + a_oc * 1024 + m0 + a_k0;
            #pragma unroll
            for (int i = 0; i < 16; i++) As[a_oc][a_k0 + i] = tf32r(wr[i]);
        }
        // stage B (im2col gather: each thread one 4x4 padded-input patch)
        {
            int ic = (m0 >> 4) + kh;
            const float* src = g_x0p + ((b * 64 + ic) * 4356) + (2 * oy) * 66 + 2 * ox;
            #pragma unroll
            for (int ky = 0; ky < 4; ky++)
                #pragma unroll
                for (int kx = 0; kx < 4; kx++)
                    Bs[kh * 16 + ky * 4 + kx][nn] = tf32r(src[ky * 66 + kx]);
        }
        __syncthreads();
        #pragma unroll
        for (int k8 = 0; k8 < 32; k8 += 8) {
            uint32_t a[4][4];
            #pragma unroll
            for (int mi = 0; mi < 4; mi++) {
                a[mi][0] = __float_as_uint(As[cw + mi * 16 + gr    ][k8 + tg    ]);
                a[mi][1] = __float_as_uint(As[cw + mi * 16 + gr + 8][k8 + tg    ]);
                a[mi][2] = __float_as_uint(As[cw + mi * 16 + gr    ][k8 + tg + 4]);
                a[mi][3] = __float_as_uint(As[cw + mi * 16 + gr + 8][k8 + tg + 4]);
            }
            uint32_t bf[4][2];
            #pragma unroll
            for (int nj = 0; nj < 4; nj++) {
                bf[nj][0] = __float_as_uint(Bs[k8 + tg    ][nw + nj * 8 + gr]);
                bf[nj][1] = __float_as_uint(Bs[k8 + tg + 4][nw + nj * 8 + gr]);
            }
            #pragma unroll
            for (int mi = 0; mi < 4; mi++)
                #pragma unroll
                for (int nj = 0; nj < 4; nj++)
                    mma_tf32(acc[mi][nj], a[mi][0], a[mi][1], a[mi][2], a[mi][3],
                             bf[nj][0], bf[nj][1]);
        }
        __syncthreads();
    }

    float* O = g_t1 + b * 128 * 1024;
    #pragma unroll
    for (int mi = 0; mi < 4; mi++) {
        int c_lo = cw + mi * 16 + gr;
        int c_hi = c_lo + 8;
        #pragma unroll
        for (int nj = 0; nj < 4; nj++) {
            int nc = n0 + nw + nj * 8 + tg * 2;
            O[c_lo * 1024 + nc]     = acc[mi][nj][0];
            O[c_lo * 1024 + nc + 1] = acc[mi][nj][1];
            O[c_hi * 1024 + nc]     = acc[mi][nj][2];
            O[c_hi * 1024 + nc + 1] = acc[mi][nj][3];
        }
    }
}

// ---------------------------------------------------------------------------
// Instance norm + leaky helper (block per (b,c)).
// ---------------------------------------------------------------------------
__device__ __forceinline__ void inorm_block(const float* x, float* y, int N) {
    float s = 0.f, s2 = 0.f;
    for (int i = threadIdx.x; i < N; i += blockDim.x) {
        float v = x[i]; s += v; s2 += v * v;
    }
    __shared__ float rs[8], rs2[8];
    #pragma unroll
    for (int o = 16; o; o >>= 1) {
        s  += __shfl_down_sync(~0u, s, o);
        s2 += __shfl_down_sync(~0u, s2, o);
    }
    int w = threadIdx.x >> 5, l = threadIdx.x & 31;
    if (l == 0) { rs[w] = s; rs2[w] = s2; }
    __syncthreads();
    if (w == 0) {
        s  = (l < (int)(blockDim.x >> 5)) ? rs[l]  : 0.f;
        s2 = (l < (int)(blockDim.x >> 5)) ? rs2[l] : 0.f;
        #pragma unroll
        for (int o = 4; o; o >>= 1) {
            s  += __shfl_down_sync(~0u, s, o);
            s2 += __shfl_down_sync(~0u, s2, o);
        }
        if (l == 0) {
            float m   = s / (float)N;
            float var = s2 / (float)N - m * m;
            rs[0]  = m;
            rs2[0] = rsqrtf(var + 1e-5f);
        }
    }
    __syncthreads();
    float m = rs[0], inv = rs2[0];
    for (int i = threadIdx.x; i < N; i += blockDim.x)
        y[i] = lrelu((x[i] - m) * inv);
}

__global__ void k_inorm1() {   // grid = B*128, block 256, N=1024
    int bc = blockIdx.x;
    inorm_block(g_t1 + bc * 1024, g_x1 + bc * 1024, 1024);
}

// ---------------------------------------------------------------------------
// K3: q/k/v 1x1 convs (scalar). grid = (4 n-tiles, 10 groups, B), block = 256.
// ---------------------------------------------------------------------------
__global__ void k_qkv(const int* __restrict__ sidx,
                      const float* __restrict__ wq, const float* __restrict__ bq,
                      const float* __restrict__ wk, const float* __restrict__ bk,
                      const float* __restrict__ wv, const float* __restrict__ bv) {
    int b = blockIdx.z;
    int g = blockIdx.y;
    int s = sidx[b];
    const float *W, *Bp;
    float* out;
    if (g == 0)      { W = wq + s * 16 * 128;  Bp = bq + s * 16;  out = g_q + b * 16 * 1024; }
    else if (g == 1) { W = wk + s * 16 * 128;  Bp = bk + s * 16;  out = g_k + b * 16 * 1024; }
    else {
        int ch0 = (g - 2) * 16;
        W   = wv + (s * 128 + ch0) * 128;
        Bp  = bv + s * 128 + ch0;
        out = g_v + (b * 128 + ch0) * 1024;
    }
    __shared__ __align__(16) float ws[128 * 16];   // [c][ch]
    __shared__ float bsm[16];
    for (int i = threadIdx.x; i < 2048; i += blockDim.x) {
        int ch = i & 15, c = i >> 4;
        ws[i] = W[ch * 128 + c];
    }
    if (threadIdx.x < 16) bsm[threadIdx.x] = Bp[threadIdx.x];
    __syncthreads();

    const float* x = g_x1 + b * 128 * 1024;
    int n = blockIdx.x * 256 + threadIdx.x;
    float acc[16];
    #pragma unroll
    for (int j = 0; j < 16; j++) acc[j] = bsm[j];
    for (int c = 0; c < 128; c++) {
        float v = x[c * 1024 + n];
        const float* wr = ws + c * 16;
        #pragma unroll
        for (int j = 0; j < 16; j += 4) {
            float4 w4 = *(const float4*)(wr + j);
            acc[j]     += v * w4.x; acc[j + 1] += v * w4.y;
            acc[j + 2] += v * w4.z; acc[j + 3] += v * w4.w;
        }
    }
    #pragma unroll
    for (int j = 0; j < 16; j++) out[j * 1024 + n] = acc[j];
}

// ---------------------------------------------------------------------------
// K4: energies + row softmax — high-MLP form (best measured: 63 us).
// ---------------------------------------------------------------------------
__global__ void k_attn_sm() {
    int b  = blockIdx.x >> 7;
    int n0 = (blockIdx.x & 127) * 8;
    __shared__ float qs[8 * 16];
    __shared__ float es[8 * 1024];   // 32KB
    if (threadIdx.x < 128) {
        int n = threadIdx.x >> 4, i = threadIdx.x & 15;
        qs[n * 16 + i] = g_q[(b * 16 + i) * 1024 + n0 + n];
    }
    __syncthreads();
    const float* kp = g_k + b * 16 * 1024;
    for (int m = threadIdx.x; m < 1024; m += 256) {
        float kv[16];
        #pragma unroll
        for (int i = 0; i < 16; i++) kv[i] = kp[i * 1024 + m];
        #pragma unroll
        for (int n = 0; n < 8; n++) {
            float e = 0.f;
            #pragma unroll
            for (int i = 0; i < 16; i++) e += qs[n * 16 + i] * kv[i];
            es[n * 1024 + m] = e;
        }
    }
    __syncthreads();
    int w = threadIdx.x >> 5, l = threadIdx.x & 31;
    float mx = -1e30f;
    for (int m = l; m < 1024; m += 32) mx = fmaxf(mx, es[w * 1024 + m]);
    #pragma unroll
    for (int o = 16; o; o >>= 1) mx = fmaxf(mx, __shfl_xor_sync(~0u, mx, o));
    float sum = 0.f;
    for (int m = l; m < 1024; m += 32) {
        float p = __expf(es[w * 1024 + m] - mx);
        es[w * 1024 + m] = p;
        sum += p;
    }
    #pragma unroll
    for (int o = 16; o; o >>= 1) sum += __shfl_xor_sync(~0u, sum, o);
    float r = 1.f / sum;
    float* out = g_attn + ((size_t)b * 1024 + n0 + w) * 1024;
    for (int m = l; m < 1024; m += 32) out[m] = es[w * 1024 + m] * r;
}

// ---------------------------------------------------------------------------
// K5: xa = gamma * (V @ attn^T) + x1 -> PADDED 34x34.   [tf32 mma.sync, R9]
// ---------------------------------------------------------------------------
__global__ void __launch_bounds__(256, 2)
k_av(const int* __restrict__ sidx, const float* __restrict__ gamma) {
    int b  = blockIdx.y;
    int n0 = blockIdx.x * 64;
    float gm = gamma[sidx[b]];
    const float* V = g_v + b * 128 * 1024;
    const float* P = g_attn + (size_t)b * 1024 * 1024;

    __shared__ __align__(16) float As[128][36];   // [c][k]
    __shared__ __align__(16) float Bs[64][36];    // [n][k]

    int tid  = threadIdx.x;
    int wid  = tid >> 5, lane = tid & 31;
    int warp_m = wid & 3;
    int warp_n = wid >> 2;
    int cw = warp_m * 32;
    int nw = warp_n * 32;
    int gr = lane >> 2;
    int tg = lane & 3;

    float acc[2][4][4] = {};

    for (int m0 = 0; m0 < 1024; m0 += 32) {
        #pragma unroll
        for (int r = 0; r < 4; r++) {
            int idx = tid + r * 256;
            int c   = idx >> 3;
            int k4  = (idx & 7) * 4;
            float4 v = *(const float4*)&V[c * 1024 + m0 + k4];
            As[c][k4 + 0] = tf32r(v.x);
            As[c][k4 + 1] = tf32r(v.y);
            As[c][k4 + 2] = tf32r(v.z);
            As[c][k4 + 3] = tf32r(v.w);
        }
        #pragma unroll
        for (int r = 0; r < 2; r++) {
            int idx = tid + r * 256;
            int n   = idx >> 3;
            int k4  = (idx & 7) * 4;
            float4 v = *(const float4*)&P[(size_t)(n0 + n) * 1024 + m0 + k4];
            Bs[n][k4 + 0] = tf32r(v.x);
            Bs[n][k4 + 1] = tf32r(v.y);
            Bs[n][k4 + 2] = tf32r(v.z);
            Bs[n][k4 + 3] = tf32r(v.w);
        }
        __syncthreads();

        #pragma unroll
        for (int k8 = 0; k8 < 32; k8 += 8) {
            uint32_t a[2][4];
            #pragma unroll
            for (int mi = 0; mi < 2; mi++) {
                a[mi][0] = __float_as_uint(As[cw + mi * 16 + gr    ][k8 + tg    ]);
                a[mi][1] = __float_as_uint(As[cw + mi * 16 + gr + 8][k8 + tg    ]);
                a[mi][2] = __float_as_uint(As[cw + mi * 16 + gr    ][k8 + tg + 4]);
                a[mi][3] = __float_as_uint(As[cw + mi * 16 + gr + 8][k8 + tg + 4]);
            }
            uint32_t bf[4][2];
            #pragma unroll
            for (int nj = 0; nj < 4; nj++) {
                bf[nj][0] = __float_as_uint(Bs[nw + nj * 8 + gr][k8 + tg    ]);
                bf[nj][1] = __float_as_uint(Bs[nw + nj * 8 + gr][k8 + tg + 4]);
            }
            #pragma unroll
            for (int mi = 0; mi < 2; mi++)
                #pragma unroll
                for (int nj = 0; nj < 4; nj++)
                    mma_tf32(acc[mi][nj], a[mi][0], a[mi][1], a[mi][2], a[mi][3],
                             bf[nj][0], bf[nj][1]);
        }
        __syncthreads();
    }

    const float* X = g_x1 + b * 128 * 1024;
    float*       O = g_xap + b * 128 * 1156;
    #pragma unroll
    for (int mi = 0; mi < 2; mi++) {
        int c_lo = cw + mi * 16 + gr;
        int c_hi = c_lo + 8;
        #pragma unroll
        for (int nj = 0; nj < 4; nj++) {
            int n = n0 + nw + nj * 8 + tg * 2;
            int y = n >> 5, x = n & 31;
            int po = (y + 1) * 34 + x + 1;
            O[c_lo * 1156 + po]     = gm * acc[mi][nj][0] + X[c_lo * 1024 + n];
            O[c_lo * 1156 + po + 1] = gm * acc[mi][nj][1] + X[c_lo * 1024 + n + 1];
            O[c_hi * 1156 + po]     = gm * acc[mi][nj][2] + X[c_hi * 1024 + n];
            O[c_hi * 1156 + po + 1] = gm * acc[mi][nj][3] + X[c_hi * 1024 + n + 1];
        }
    }
}

// ---------------------------------------------------------------------------
// K6: conv2 as tf32 implicit GEMM with split-K.
// C[128oc x 128n] per CTA over a K-slice of 512 (32 ic). K-chunk 16 (1 ic).
// grid = (4 K-slices, 4 tiles [mt*2+nt], B), block = 256 (8 warps, 2m x 4n).
// Partials -> g_t2p[ks]. Bias dropped (cancels under inorm).
// ---------------------------------------------------------------------------
__global__ void __launch_bounds__(256, 2)
k_conv2g(const int* __restrict__ sidx, const float* __restrict__ w2) {
    int ks = blockIdx.x;          // K slice 0..3
    int mt = blockIdx.y >> 1;     // 0..1 oc tile
    int nt = blockIdx.y & 1;      // 0..1 n tile
    int b  = blockIdx.z;
    int s  = sidx[b];
    __shared__ __align__(16) float As[128][20];   // weights [oc][k16]  10.2KB
    __shared__ __align__(16) float Bs[16][136];   // patches [k][n]      8.7KB

    int tid  = threadIdx.x;
    int wid  = tid >> 5, lane = tid & 31;
    int warp_m = wid >> 2;        // 0..1
    int warp_n = wid & 3;         // 0..3
    int cw = warp_m * 64;
    int nw = warp_n * 32;
    int gr = lane >> 2, tg = lane & 3;

    float acc[4][4][4] = {};

    // gather coords
    int nn = tid & 127, half = tid >> 7;   // half: which 8 of the 16 k
    int n  = nt * 128 + nn;
    int oy = n >> 4, ox = n & 15;
    const float* wbase = w2 + (size_t)(s * 256 + mt * 128) * 2048 + ks * 512;
    int a_oc = tid >> 1, a_k0 = (tid & 1) * 8;

    for (int cc = 0; cc < 32; cc++) {      // 32 chunks of K=16 (one ic each)
        int ic = ks * 32 + cc;
        // stage A (weights 128x16, coalesced)
        {
            const float* wr = wbase + a_oc * 2048 + cc * 16 + a_k0;
            #pragma unroll
            for (int i = 0; i < 8; i++) As[a_oc][a_k0 + i] = tf32r(wr[i]);
        }
        // stage B (each thread: 2 rows x 4 cols of the 4x4 patch)
        {
            const float* src = g_xap + ((b * 128 + ic) * 1156) + (2 * oy) * 34 + 2 * ox;
            #pragma unroll
            for (int dy = 0; dy < 2; dy++)
                #pragma unroll
                for (int kx = 0; kx < 4; kx++)
                    Bs[half * 8 + dy * 4 + kx][nn] =
                        tf32r(src[(half * 2 + dy) * 34 + kx]);
        }
        __syncthreads();
        #pragma unroll
        for (int k8 = 0; k8 < 16; k8 += 8) {
            uint32_t a[4][4];
            #pragma unroll
            for (int mi = 0; mi < 4; mi++) {
                a[mi][0] = __float_as_uint(As[cw + mi * 16 + gr    ][k8 + tg    ]);
                a[mi][1] = __float_as_uint(As[cw + mi * 16 + gr + 8][k8 + tg    ]);
                a[mi][2] = __float_as_uint(As[cw + mi * 16 + gr    ][k8 + tg + 4]);
                a[mi][3] = __float_as_uint(As[cw + mi * 16 + gr + 8][k8 + tg + 4]);
            }
            uint32_t bf[4][2];
            #pragma unroll
            for (int nj = 0; nj < 4; nj++) {
                bf[nj][0] = __float_as_uint(Bs[k8 + tg    ][nw + nj * 8 + gr]);
                bf[nj][1] = __float_as_uint(Bs[k8 + tg + 4][nw + nj * 8 + gr]);
            }
            #pragma unroll
            for (int mi = 0; mi < 4; mi++)
                #pragma unroll
                for (int nj = 0; nj < 4; nj++)
                    mma_tf32(acc[mi][nj], a[mi][0], a[mi][1], a[mi][2], a[mi][3],
                             bf[nj][0], bf[nj][1]);
        }
        __syncthreads();
    }

    float* O = g_t2p + ((size_t)(ks * B_ + b) * 256 + mt * 128) * 256;
    #pragma unroll
    for (int mi = 0; mi < 4; mi++) {
        int c_lo = cw + mi * 16 + gr;
        int c_hi = c_lo + 8;
        #pragma unroll
        for (int nj = 0; nj < 4; nj++) {
            int nc = nt * 128 + nw + nj * 8 + tg * 2;
            O[c_lo * 256 + nc]     = acc[mi][nj][0];
            O[c_lo * 256 + nc + 1] = acc[mi][nj][1];
            O[c_hi * 256 + nc]     = acc[mi][nj][2];
            O[c_hi * 256 + nc + 1] = acc[mi][nj][3];
        }
    }
}

// ---------------------------------------------------------------------------
// K6b: sum 4 K-split partials + instance norm + leaky -> g_x2.
// grid = B*256 (one block per (b, oc)), block = 256 (one elem per thread).
// ---------------------------------------------------------------------------
__global__ void k_inorm2() {
    int b = blockIdx.x >> 8;
    int c = blockIdx.x & 255;
    int t = threadIdx.x;
    float v = 0.f;
    #pragma unroll
    for (int ks = 0; ks < 4; ks++)
        v += g_t2p[((size_t)(ks * B_ + b) * 256 + c) * 256 + t];

    float sv = v, qv = v * v;
    __shared__ float rs[8], rs2[8];
    #pragma unroll
    for (int o = 16; o; o >>= 1) {
        sv += __shfl_down_sync(~0u, sv, o);
        qv += __shfl_down_sync(~0u, qv, o);
    }
    int w = t >> 5, l = t & 31;
    if (l == 0) { rs[w] = sv; rs2[w] = qv; }
    __syncthreads();
    if (w == 0) {
        sv = (l < 8) ? rs[l]  : 0.f;
        qv = (l < 8) ? rs2[l] : 0.f;
        #pragma unroll
        for (int o = 4; o; o >>= 1) {
            sv += __shfl_down_sync(~0u, sv, o);
            qv += __shfl_down_sync(~0u, qv, o);
        }
        if (l == 0) {
            float m   = sv * (1.f / 256.f);
            float var = qv * (1.f / 256.f) - m * m;
            rs[0]  = m;
            rs2[0] = rsqrtf(var + 1e-5f);
        }
    }
    __syncthreads();
    g_x2[(b * 256 + c) * 256 + t] = lrelu((v - rs[0]) * rs2[0]);
}

// ---------------------------------------------------------------------------
// K7: head conv (256->1, k4 s1 p1, 16->15). grid = B, block = 256 (225 used).
// ---------------------------------------------------------------------------
__global__ void k_head(const int* __restrict__ sidx,
                       const float* __restrict__ wh, const float* __restrict__ bh,
                       float* __restrict__ out) {
    int b = blockIdx.x;
    int s = sidx[b];
    __shared__ float ws[256 * 16];
    for (int i = threadIdx.x; i < 4096; i += blockDim.x) ws[i] = wh[s * 4096 + i];
    __shared__ float bias;
    if (threadIdx.x == 0) bias = bh[s];
    __syncthreads();
    if (threadIdx.x < 225) {
        int oy = threadIdx.x / 15, ox = threadIdx.x % 15;
        float acc = bias;
        const float* x = g_x2 + b * 256 * 256;
        for (int ic = 0; ic < 256; ic++) {
            const float* xc = x + ic * 256;
            const float* wr = ws + ic * 16;
            #pragma unroll
            for (int ky = 0; ky < 4; ky++) {
                int iy = oy - 1 + ky;
                if ((unsigned)iy < 16u) {
                    #pragma unroll
                    for (int kx = 0; kx < 4; kx++) {
                        int ix = ox - 1 + kx;
                        if ((unsigned)ix < 16u)
                            acc += xc[iy * 16 + ix] * wr[ky * 4 + kx];
                    }
                }
            }
        }
        out[b * 225 + threadIdx.x] = acc;
    }
}

// ---------------------------------------------------------------------------
extern "C" void kernel_launch(void* const* d_in, const int* in_sizes, int n_in,
                              void* d_out, int out_size) {
    const float* img  = (const float*)d_in[0];
    const int*   sidx = (const int*)  d_in[1];
    const float* w0 = (const float*)d_in[2];
    const float* b0 = (const float*)d_in[3];
    const float* w1 = (const float*)d_in[4];
    const float* w2 = (const float*)d_in[6];
    const float* wq = (const float*)d_in[8];
    const float* bq = (const float*)d_in[9];
    const float* wk = (const float*)d_in[10];
    const float* bk = (const float*)d_in[11];
    const float* wv = (const float*)d_in[12];
    const float* bv = (const float*)d_in[13];
    const float* gamma = (const float*)d_in[14];
    const float* wh = (const float*)d_in[15];
    const float* bh = (const float*)d_in[16];
    float* out = (float*)d_out;

    k_conv0   <<<B_ * 64, 256>>>(img, sidx, w0, b0);
    k_conv1g  <<<dim3(8, B_), 256>>>(sidx, w1);
    k_inorm1  <<<B_ * 128, 256>>>();
    k_qkv     <<<dim3(4, 10, B_), 256>>>(sidx, wq, bq, wk, bk, wv, bv);
    k_attn_sm <<<B_ * 128, 256>>>();
    k_av      <<<dim3(16, B_), 256>>>(sidx, gamma);
    k_conv2g  <<<dim3(4, 4, B_), 256>>>(sidx, w2);
    k_inorm2  <<<B_ * 256, 256>>>();
    k_head    <<<B_, 256>>>(sidx, wh, bh, out);
}

// round 11
// speedup vs baseline: 2.0820x; 1.0149x over previous
#include <cuda_runtime.h>
#include <cuda_bf16.h>
#include <cstdint>

// ---------------------------------------------------------------------------
// MultiStageDiscriminator — tf32 mma for conv1/conv2/AV/V-proj; scalar rest.
// ---------------------------------------------------------------------------

#define B_ 16
#define SLOPE 0.2f

// ---- static scratch (zero-initialized; padded borders are never written) ----
__device__ float g_x0p[B_ * 64 * 66 * 66];     // conv0 out, padded 66x66
__device__ float g_t1 [B_ * 128 * 1024];       // conv1 raw (pre-norm)
__device__ float g_x1 [B_ * 128 * 1024];       // post inorm+leaky
__device__ float g_q  [B_ * 16 * 1024];
__device__ float g_k  [B_ * 16 * 1024];
__device__ float g_v  [B_ * 128 * 1024];
__device__ float g_attn[B_ * 1024 * 1024];     // 64 MB
__device__ float g_xap[B_ * 128 * 34 * 34];    // attn residual out, padded 34x34
__device__ float g_t2p[4 * B_ * 256 * 256];    // conv2 K-split partials
__device__ float g_x2 [B_ * 256 * 16 * 16];

__device__ __forceinline__ float lrelu(float v) { return v > 0.f ? v : SLOPE * v; }

__device__ __forceinline__ float tf32r(float x) {
    float r; asm("cvt.rna.tf32.f32 %0, %1;" : "=f"(r) : "f"(x)); return r;
}

__device__ __forceinline__ void mma_tf32(float d[4],
                                         uint32_t a0, uint32_t a1, uint32_t a2, uint32_t a3,
                                         uint32_t b0, uint32_t b1) {
    asm volatile(
        "mma.sync.aligned.m16n8k8.row.col.f32.tf32.tf32.f32 "
        "{%0,%1,%2,%3}, {%4,%5,%6,%7}, {%8,%9}, {%0,%1,%2,%3};\n"
        : "+f"(d[0]), "+f"(d[1]), "+f"(d[2]), "+f"(d[3])
        : "r"(a0), "r"(a1), "r"(a2), "r"(a3), "r"(b0), "r"(b1));
}

// ---------------------------------------------------------------------------
// K1: conv0 (1->64, k4 s2 p1, 128->64) + leaky -> padded 66x66.
// ---------------------------------------------------------------------------
__global__ void k_conv0(const float* __restrict__ img, const int* __restrict__ sidx,
                        const float* __restrict__ w0, const float* __restrict__ b0) {
    int b  = blockIdx.x >> 6;
    int oc = blockIdx.x & 63;
    int s  = sidx[b];
    __shared__ float ws[16];
    __shared__ float bias;
    if (threadIdx.x < 16) ws[threadIdx.x] = w0[(s * 64 + oc) * 16 + threadIdx.x];
    if (threadIdx.x == 0) bias = b0[s * 64 + oc];
    __syncthreads();
    const float* im  = img + b * 128 * 128;
    float*       out = g_x0p + (b * 64 + oc) * 4356;
    for (int p = threadIdx.x; p < 4096; p += blockDim.x) {
        int oy = p >> 6, ox = p & 63;
        float acc = bias;
        #pragma unroll
        for (int ky = 0; ky < 4; ky++) {
            int iy = 2 * oy - 1 + ky;
            if ((unsigned)iy < 128u) {
                #pragma unroll
                for (int kx = 0; kx < 4; kx++) {
                    int ix = 2 * ox - 1 + kx;
                    if ((unsigned)ix < 128u)
                        acc += im[iy * 128 + ix] * ws[ky * 4 + kx];
                }
            }
        }
        out[(oy + 1) * 66 + ox + 1] = lrelu(acc);
    }
}

// ---------------------------------------------------------------------------
// K2: conv1 as tf32 implicit GEMM (unchanged from R10).
// ---------------------------------------------------------------------------
__global__ void __launch_bounds__(256, 2)
k_conv1g(const int* __restrict__ sidx, const float* __restrict__ w1) {
    int b  = blockIdx.y;
    int n0 = blockIdx.x * 128;
    int s  = sidx[b];
    __shared__ __align__(16) float As[128][36];
    __shared__ __align__(16) float Bs[32][136];

    int tid  = threadIdx.x;
    int wid  = tid >> 5, lane = tid & 31;
    int warp_m = wid >> 2;
    int warp_n = wid & 3;
    int cw = warp_m * 64;
    int nw = warp_n * 32;
    int gr = lane >> 2, tg = lane & 3;

    float acc[4][4][4] = {};

    int nn = tid & 127, kh = tid >> 7;
    int n  = n0 + nn;
    int oy = n >> 5, ox = n & 31;
    const float* wbase = w1 + (size_t)(s * 128) * 1024;
    int a_oc = tid >> 1, a_k0 = (tid & 1) * 16;

    for (int m0 = 0; m0 < 1024; m0 += 32) {
        {
            const float* wr = wbase + a_oc * 1024 + m0 + a_k0;
            #pragma unroll
            for (int i = 0; i < 16; i++) As[a_oc][a_k0 + i] = tf32r(wr[i]);
        }
        {
            int ic = (m0 >> 4) + kh;
            const float* src = g_x0p + ((b * 64 + ic) * 4356) + (2 * oy) * 66 + 2 * ox;
            #pragma unroll
            for (int ky = 0; ky < 4; ky++)
                #pragma unroll
                for (int kx = 0; kx < 4; kx++)
                    Bs[kh * 16 + ky * 4 + kx][nn] = tf32r(src[ky * 66 + kx]);
        }
        __syncthreads();
        #pragma unroll
        for (int k8 = 0; k8 < 32; k8 += 8) {
            uint32_t a[4][4];
            #pragma unroll
            for (int mi = 0; mi < 4; mi++) {
                a[mi][0] = __float_as_uint(As[cw + mi * 16 + gr    ][k8 + tg    ]);
                a[mi][1] = __float_as_uint(As[cw + mi * 16 + gr + 8][k8 + tg    ]);
                a[mi][2] = __float_as_uint(As[cw + mi * 16 + gr    ][k8 + tg + 4]);
                a[mi][3] = __float_as_uint(As[cw + mi * 16 + gr + 8][k8 + tg + 4]);
            }
            uint32_t bf[4][2];
            #pragma unroll
            for (int nj = 0; nj < 4; nj++) {
                bf[nj][0] = __float_as_uint(Bs[k8 + tg    ][nw + nj * 8 + gr]);
                bf[nj][1] = __float_as_uint(Bs[k8 + tg + 4][nw + nj * 8 + gr]);
            }
            #pragma unroll
            for (int mi = 0; mi < 4; mi++)
                #pragma unroll
                for (int nj = 0; nj < 4; nj++)
                    mma_tf32(acc[mi][nj], a[mi][0], a[mi][1], a[mi][2], a[mi][3],
                             bf[nj][0], bf[nj][1]);
        }
        __syncthreads();
    }

    float* O = g_t1 + b * 128 * 1024;
    #pragma unroll
    for (int mi = 0; mi < 4; mi++) {
        int c_lo = cw + mi * 16 + gr;
        int c_hi = c_lo + 8;
        #pragma unroll
        for (int nj = 0; nj < 4; nj++) {
            int nc = n0 + nw + nj * 8 + tg * 2;
            O[c_lo * 1024 + nc]     = acc[mi][nj][0];
            O[c_lo * 1024 + nc + 1] = acc[mi][nj][1];
            O[c_hi * 1024 + nc]     = acc[mi][nj][2];
            O[c_hi * 1024 + nc + 1] = acc[mi][nj][3];
        }
    }
}

// ---------------------------------------------------------------------------
// Instance norm + leaky helper (block per (b,c)).
// ---------------------------------------------------------------------------
__device__ __forceinline__ void inorm_block(const float* x, float* y, int N) {
    float s = 0.f, s2 = 0.f;
    for (int i = threadIdx.x; i < N; i += blockDim.x) {
        float v = x[i]; s += v; s2 += v * v;
    }
    __shared__ float rs[8], rs2[8];
    #pragma unroll
    for (int o = 16; o; o >>= 1) {
        s  += __shfl_down_sync(~0u, s, o);
        s2 += __shfl_down_sync(~0u, s2, o);
    }
    int w = threadIdx.x >> 5, l = threadIdx.x & 31;
    if (l == 0) { rs[w] = s; rs2[w] = s2; }
    __syncthreads();
    if (w == 0) {
        s  = (l < (int)(blockDim.x >> 5)) ? rs[l]  : 0.f;
        s2 = (l < (int)(blockDim.x >> 5)) ? rs2[l] : 0.f;
        #pragma unroll
        for (int o = 4; o; o >>= 1) {
            s  += __shfl_down_sync(~0u, s, o);
            s2 += __shfl_down_sync(~0u, s2, o);
        }
        if (l == 0) {
            float m   = s / (float)N;
            float var = s2 / (float)N - m * m;
            rs[0]  = m;
            rs2[0] = rsqrtf(var + 1e-5f);
        }
    }
    __syncthreads();
    float m = rs[0], inv = rs2[0];
    for (int i = threadIdx.x; i < N; i += blockDim.x)
        y[i] = lrelu((x[i] - m) * inv);
}

__global__ void k_inorm1() {
    int bc = blockIdx.x;
    inorm_block(g_t1 + bc * 1024, g_x1 + bc * 1024, 1024);
}

// ---------------------------------------------------------------------------
// K3a: q/k 1x1 convs (scalar, 16 ch each). grid = (4 n-tiles, 2, B).
// ---------------------------------------------------------------------------
__global__ void k_qk(const int* __restrict__ sidx,
                     const float* __restrict__ wq, const float* __restrict__ bq,
                     const float* __restrict__ wk, const float* __restrict__ bk) {
    int b = blockIdx.z;
    int g = blockIdx.y;
    int s = sidx[b];
    const float *W, *Bp;
    float* out;
    if (g == 0) { W = wq + s * 16 * 128; Bp = bq + s * 16; out = g_q + b * 16 * 1024; }
    else        { W = wk + s * 16 * 128; Bp = bk + s * 16; out = g_k + b * 16 * 1024; }
    __shared__ __align__(16) float ws[128 * 16];   // [c][ch]
    __shared__ float bsm[16];
    for (int i = threadIdx.x; i < 2048; i += blockDim.x) {
        int ch = i & 15, c = i >> 4;
        ws[i] = W[ch * 128 + c];
    }
    if (threadIdx.x < 16) bsm[threadIdx.x] = Bp[threadIdx.x];
    __syncthreads();

    const float* x = g_x1 + b * 128 * 1024;
    int n = blockIdx.x * 256 + threadIdx.x;
    float acc[16];
    #pragma unroll
    for (int j = 0; j < 16; j++) acc[j] = bsm[j];
    for (int c = 0; c < 128; c++) {
        float v = x[c * 1024 + n];
        const float* wr = ws + c * 16;
        #pragma unroll
        for (int j = 0; j < 16; j += 4) {
            float4 w4 = *(const float4*)(wr + j);
            acc[j]     += v * w4.x; acc[j + 1] += v * w4.y;
            acc[j + 2] += v * w4.z; acc[j + 3] += v * w4.w;
        }
    }
    #pragma unroll
    for (int j = 0; j < 16; j++) out[j * 1024 + n] = acc[j];
}

// ---------------------------------------------------------------------------
// K3b: V projection as tf32 GEMM: g_v[128ch x 1024n] = Wv[128x128] @ x1 + bv.
// grid = (8 n-tiles, B), block = 256 (8 warps, 2m x 4n), K=128 in 4 chunks.
// ---------------------------------------------------------------------------
__global__ void __launch_bounds__(256, 2)
k_vmma(const int* __restrict__ sidx,
       const float* __restrict__ wv, const float* __restrict__ bv) {
    int b  = blockIdx.y;
    int n0 = blockIdx.x * 128;
    int s  = sidx[b];
    __shared__ __align__(16) float As[128][36];   // Wv [ch][c-chunk]
    __shared__ __align__(16) float Bs[32][136];   // x1 [c][n]

    int tid  = threadIdx.x;
    int wid  = tid >> 5, lane = tid & 31;
    int warp_m = wid >> 2;
    int warp_n = wid & 3;
    int cw = warp_m * 64;
    int nw = warp_n * 32;
    int gr = lane >> 2, tg = lane & 3;

    float acc[4][4][4] = {};

    const float* wbase = wv + (size_t)(s * 128) * 128;
    const float* x     = g_x1 + b * 128 * 1024;
    int a_ch = tid >> 1, a_k0 = (tid & 1) * 16;

    for (int c0 = 0; c0 < 128; c0 += 32) {
        {
            const float* wr = wbase + a_ch * 128 + c0 + a_k0;
            #pragma unroll
            for (int i = 0; i < 16; i++) As[a_ch][a_k0 + i] = tf32r(wr[i]);
        }
        #pragma unroll
        for (int r = 0; r < 16; r++) {
            int idx = tid + r * 256;
            int c = idx >> 7, nn = idx & 127;
            Bs[c][nn] = tf32r(x[(c0 + c) * 1024 + n0 + nn]);
        }
        __syncthreads();
        #pragma unroll
        for (int k8 = 0; k8 < 32; k8 += 8) {
            uint32_t a[4][4];
            #pragma unroll
            for (int mi = 0; mi < 4; mi++) {
                a[mi][0] = __float_as_uint(As[cw + mi * 16 + gr    ][k8 + tg    ]);
                a[mi][1] = __float_as_uint(As[cw + mi * 16 + gr + 8][k8 + tg    ]);
                a[mi][2] = __float_as_uint(As[cw + mi * 16 + gr    ][k8 + tg + 4]);
                a[mi][3] = __float_as_uint(As[cw + mi * 16 + gr + 8][k8 + tg + 4]);
            }
            uint32_t bf[4][2];
            #pragma unroll
            for (int nj = 0; nj < 4; nj++) {
                bf[nj][0] = __float_as_uint(Bs[k8 + tg    ][nw + nj * 8 + gr]);
                bf[nj][1] = __float_as_uint(Bs[k8 + tg + 4][nw + nj * 8 + gr]);
            }
            #pragma unroll
            for (int mi = 0; mi < 4; mi++)
                #pragma unroll
                for (int nj = 0; nj < 4; nj++)
                    mma_tf32(acc[mi][nj], a[mi][0], a[mi][1], a[mi][2], a[mi][3],
                             bf[nj][0], bf[nj][1]);
        }
        __syncthreads();
    }

    const float* bvp = bv + s * 128;
    float* O = g_v + b * 128 * 1024;
    #pragma unroll
    for (int mi = 0; mi < 4; mi++) {
        int c_lo = cw + mi * 16 + gr;
        int c_hi = c_lo + 8;
        float bl = bvp[c_lo], bh = bvp[c_hi];
        #pragma unroll
        for (int nj = 0; nj < 4; nj++) {
            int nc = n0 + nw + nj * 8 + tg * 2;
            O[c_lo * 1024 + nc]     = acc[mi][nj][0] + bl;
            O[c_lo * 1024 + nc + 1] = acc[mi][nj][1] + bl;
            O[c_hi * 1024 + nc]     = acc[mi][nj][2] + bh;
            O[c_hi * 1024 + nc + 1] = acc[mi][nj][3] + bh;
        }
    }
}

// ---------------------------------------------------------------------------
// K4: energies + row softmax. unroll 2 on m-loop: ~100 regs -> 2 CTAs/SM
// while keeping 32 loads in flight per iteration.
// ---------------------------------------------------------------------------
__global__ void k_attn_sm() {
    int b  = blockIdx.x >> 7;
    int n0 = (blockIdx.x & 127) * 8;
    __shared__ float qs[8 * 16];
    __shared__ float es[8 * 1024];   // 32KB
    if (threadIdx.x < 128) {
        int n = threadIdx.x >> 4, i = threadIdx.x & 15;
        qs[n * 16 + i] = g_q[(b * 16 + i) * 1024 + n0 + n];
    }
    __syncthreads();
    const float* kp = g_k + b * 16 * 1024;
    #pragma unroll 2
    for (int m = threadIdx.x; m < 1024; m += 256) {
        float kv[16];
        #pragma unroll
        for (int i = 0; i < 16; i++) kv[i] = kp[i * 1024 + m];
        #pragma unroll
        for (int n = 0; n < 8; n++) {
            float e = 0.f;
            #pragma unroll
            for (int i = 0; i < 16; i++) e += qs[n * 16 + i] * kv[i];
            es[n * 1024 + m] = e;
        }
    }
    __syncthreads();
    int w = threadIdx.x >> 5, l = threadIdx.x & 31;
    float mx = -1e30f;
    for (int m = l; m < 1024; m += 32) mx = fmaxf(mx, es[w * 1024 + m]);
    #pragma unroll
    for (int o = 16; o; o >>= 1) mx = fmaxf(mx, __shfl_xor_sync(~0u, mx, o));
    float sum = 0.f;
    for (int m = l; m < 1024; m += 32) {
        float p = __expf(es[w * 1024 + m] - mx);
        es[w * 1024 + m] = p;
        sum += p;
    }
    #pragma unroll
    for (int o = 16; o; o >>= 1) sum += __shfl_xor_sync(~0u, sum, o);
    float r = 1.f / sum;
    float* out = g_attn + ((size_t)b * 1024 + n0 + w) * 1024;
    for (int m = l; m < 1024; m += 32) out[m] = es[w * 1024 + m] * r;
}

// ---------------------------------------------------------------------------
// K5: xa = gamma * (V @ attn^T) + x1 -> PADDED 34x34.   [tf32 mma.sync, R9]
// ---------------------------------------------------------------------------
__global__ void __launch_bounds__(256, 2)
k_av(const int* __restrict__ sidx, const float* __restrict__ gamma) {
    int b  = blockIdx.y;
    int n0 = blockIdx.x * 64;
    float gm = gamma[sidx[b]];
    const float* V = g_v + b * 128 * 1024;
    const float* P = g_attn + (size_t)b * 1024 * 1024;

    __shared__ __align__(16) float As[128][36];
    __shared__ __align__(16) float Bs[64][36];

    int tid  = threadIdx.x;
    int wid  = tid >> 5, lane = tid & 31;
    int warp_m = wid & 3;
    int warp_n = wid >> 2;
    int cw = warp_m * 32;
    int nw = warp_n * 32;
    int gr = lane >> 2;
    int tg = lane & 3;

    float acc[2][4][4] = {};

    for (int m0 = 0; m0 < 1024; m0 += 32) {
        #pragma unroll
        for (int r = 0; r < 4; r++) {
            int idx = tid + r * 256;
            int c   = idx >> 3;
            int k4  = (idx & 7) * 4;
            float4 v = *(const float4*)&V[c * 1024 + m0 + k4];
            As[c][k4 + 0] = tf32r(v.x);
            As[c][k4 + 1] = tf32r(v.y);
            As[c][k4 + 2] = tf32r(v.z);
            As[c][k4 + 3] = tf32r(v.w);
        }
        #pragma unroll
        for (int r = 0; r < 2; r++) {
            int idx = tid + r * 256;
            int n   = idx >> 3;
            int k4  = (idx & 7) * 4;
            float4 v = *(const float4*)&P[(size_t)(n0 + n) * 1024 + m0 + k4];
            Bs[n][k4 + 0] = tf32r(v.x);
            Bs[n][k4 + 1] = tf32r(v.y);
            Bs[n][k4 + 2] = tf32r(v.z);
            Bs[n][k4 + 3] = tf32r(v.w);
        }
        __syncthreads();

        #pragma unroll
        for (int k8 = 0; k8 < 32; k8 += 8) {
            uint32_t a[2][4];
            #pragma unroll
            for (int mi = 0; mi < 2; mi++) {
                a[mi][0] = __float_as_uint(As[cw + mi * 16 + gr    ][k8 + tg    ]);
                a[mi][1] = __float_as_uint(As[cw + mi * 16 + gr + 8][k8 + tg    ]);
                a[mi][2] = __float_as_uint(As[cw + mi * 16 + gr    ][k8 + tg + 4]);
                a[mi][3] = __float_as_uint(As[cw + mi * 16 + gr + 8][k8 + tg + 4]);
            }
            uint32_t bf[4][2];
            #pragma unroll
            for (int nj = 0; nj < 4; nj++) {
                bf[nj][0] = __float_as_uint(Bs[nw + nj * 8 + gr][k8 + tg    ]);
                bf[nj][1] = __float_as_uint(Bs[nw + nj * 8 + gr][k8 + tg + 4]);
            }
            #pragma unroll
            for (int mi = 0; mi < 2; mi++)
                #pragma unroll
                for (int nj = 0; nj < 4; nj++)
                    mma_tf32(acc[mi][nj], a[mi][0], a[mi][1], a[mi][2], a[mi][3],
                             bf[nj][0], bf[nj][1]);
        }
        __syncthreads();
    }

    const float* X = g_x1 + b * 128 * 1024;
    float*       O = g_xap + b * 128 * 1156;
    #pragma unroll
    for (int mi = 0; mi < 2; mi++) {
        int c_lo = cw + mi * 16 + gr;
        int c_hi = c_lo + 8;
        #pragma unroll
        for (int nj = 0; nj < 4; nj++) {
            int n = n0 + nw + nj * 8 + tg * 2;
            int y = n >> 5, x = n & 31;
            int po = (y + 1) * 34 + x + 1;
            O[c_lo * 1156 + po]     = gm * acc[mi][nj][0] + X[c_lo * 1024 + n];
            O[c_lo * 1156 + po + 1] = gm * acc[mi][nj][1] + X[c_lo * 1024 + n + 1];
            O[c_hi * 1156 + po]     = gm * acc[mi][nj][2] + X[c_hi * 1024 + n];
            O[c_hi * 1156 + po + 1] = gm * acc[mi][nj][3] + X[c_hi * 1024 + n + 1];
        }
    }
}

// ---------------------------------------------------------------------------
// K6: conv2 as tf32 implicit GEMM with split-K (unchanged from R10).
// ---------------------------------------------------------------------------
__global__ void __launch_bounds__(256, 2)
k_conv2g(const int* __restrict__ sidx, const float* __restrict__ w2) {
    int ks = blockIdx.x;
    int mt = blockIdx.y >> 1;
    int nt = blockIdx.y & 1;
    int b  = blockIdx.z;
    int s  = sidx[b];
    __shared__ __align__(16) float As[128][20];
    __shared__ __align__(16) float Bs[16][136];

    int tid  = threadIdx.x;
    int wid  = tid >> 5, lane = tid & 31;
    int warp_m = wid >> 2;
    int warp_n = wid & 3;
    int cw = warp_m * 64;
    int nw = warp_n * 32;
    int gr = lane >> 2, tg = lane & 3;

    float acc[4][4][4] = {};

    int nn = tid & 127, half = tid >> 7;
    int n  = nt * 128 + nn;
    int oy = n >> 4, ox = n & 15;
    const float* wbase = w2 + (size_t)(s * 256 + mt * 128) * 2048 + ks * 512;
    int a_oc = tid >> 1, a_k0 = (tid & 1) * 8;

    for (int cc = 0; cc < 32; cc++) {
        int ic = ks * 32 + cc;
        {
            const float* wr = wbase + a_oc * 2048 + cc * 16 + a_k0;
            #pragma unroll
            for (int i = 0; i < 8; i++) As[a_oc][a_k0 + i] = tf32r(wr[i]);
        }
        {
            const float* src = g_xap + ((b * 128 + ic) * 1156) + (2 * oy) * 34 + 2 * ox;
            #pragma unroll
            for (int dy = 0; dy < 2; dy++)
                #pragma unroll
                for (int kx = 0; kx < 4; kx++)
                    Bs[half * 8 + dy * 4 + kx][nn] =
                        tf32r(src[(half * 2 + dy) * 34 + kx]);
        }
        __syncthreads();
        #pragma unroll
        for (int k8 = 0; k8 < 16; k8 += 8) {
            uint32_t a[4][4];
            #pragma unroll
            for (int mi = 0; mi < 4; mi++) {
                a[mi][0] = __float_as_uint(As[cw + mi * 16 + gr    ][k8 + tg    ]);
                a[mi][1] = __float_as_uint(As[cw + mi * 16 + gr + 8][k8 + tg    ]);
                a[mi][2] = __float_as_uint(As[cw + mi * 16 + gr    ][k8 + tg + 4]);
                a[mi][3] = __float_as_uint(As[cw + mi * 16 + gr + 8][k8 + tg + 4]);
            }
            uint32_t bf[4][2];
            #pragma unroll
            for (int nj = 0; nj < 4; nj++) {
                bf[nj][0] = __float_as_uint(Bs[k8 + tg    ][nw + nj * 8 + gr]);
                bf[nj][1] = __float_as_uint(Bs[k8 + tg + 4][nw + nj * 8 + gr]);
            }
            #pragma unroll
            for (int mi = 0; mi < 4; mi++)
                #pragma unroll
                for (int nj = 0; nj < 4; nj++)
                    mma_tf32(acc[mi][nj], a[mi][0], a[mi][1], a[mi][2], a[mi][3],
                             bf[nj][0], bf[nj][1]);
        }
        __syncthreads();
    }

    float* O = g_t2p + ((size_t)(ks * B_ + b) * 256 + mt * 128) * 256;
    #pragma unroll
    for (int mi = 0; mi < 4; mi++) {
        int c_lo = cw + mi * 16 + gr;
        int c_hi = c_lo + 8;
        #pragma unroll
        for (int nj = 0; nj < 4; nj++) {
            int nc = nt * 128 + nw + nj * 8 + tg * 2;
            O[c_lo * 256 + nc]     = acc[mi][nj][0];
            O[c_lo * 256 + nc + 1] = acc[mi][nj][1];
            O[c_hi * 256 + nc]     = acc[mi][nj][2];
            O[c_hi * 256 + nc + 1] = acc[mi][nj][3];
        }
    }
}

// ---------------------------------------------------------------------------
// K6b: sum 4 K-split partials + instance norm + leaky -> g_x2.
// ---------------------------------------------------------------------------
__global__ void k_inorm2() {
    int b = blockIdx.x >> 8;
    int c = blockIdx.x & 255;
    int t = threadIdx.x;
    float v = 0.f;
    #pragma unroll
    for (int ks = 0; ks < 4; ks++)
        v += g_t2p[((size_t)(ks * B_ + b) * 256 + c) * 256 + t];

    float sv = v, qv = v * v;
    __shared__ float rs[8], rs2[8];
    #pragma unroll
    for (int o = 16; o; o >>= 1) {
        sv += __shfl_down_sync(~0u, sv, o);
        qv += __shfl_down_sync(~0u, qv, o);
    }
    int w = t >> 5, l = t & 31;
    if (l == 0) { rs[w] = sv; rs2[w] = qv; }
    __syncthreads();
    if (w == 0) {
        sv = (l < 8) ? rs[l]  : 0.f;
        qv = (l < 8) ? rs2[l] : 0.f;
        #pragma unroll
        for (int o = 4; o; o >>= 1) {
            sv += __shfl_down_sync(~0u, sv, o);
            qv += __shfl_down_sync(~0u, qv, o);
        }
        if (l == 0) {
            float m   = sv * (1.f / 256.f);
            float var = qv * (1.f / 256.f) - m * m;
            rs[0]  = m;
            rs2[0] = rsqrtf(var + 1e-5f);
        }
    }
    __syncthreads();
    g_x2[(b * 256 + c) * 256 + t] = lrelu((v - rs[0]) * rs2[0]);
}

// ---------------------------------------------------------------------------
// K7: head conv (256->1, k4 s1 p1, 16->15). grid = B, block = 256 (225 used).
// ---------------------------------------------------------------------------
__global__ void k_head(const int* __restrict__ sidx,
                       const float* __restrict__ wh, const float* __restrict__ bh,
                       float* __restrict__ out) {
    int b = blockIdx.x;
    int s = sidx[b];
    __shared__ float ws[256 * 16];
    for (int i = threadIdx.x; i < 4096; i += blockDim.x) ws[i] = wh[s * 4096 + i];
    __shared__ float bias;
    if (threadIdx.x == 0) bias = bh[s];
    __syncthreads();
    if (threadIdx.x < 225) {
        int oy = threadIdx.x / 15, ox = threadIdx.x % 15;
        float acc = bias;
        const float* x = g_x2 + b * 256 * 256;
        for (int ic = 0; ic < 256; ic++) {
            const float* xc = x + ic * 256;
            const float* wr = ws + ic * 16;
            #pragma unroll
            for (int ky = 0; ky < 4; ky++) {
                int iy = oy - 1 + ky;
                if ((unsigned)iy < 16u) {
                    #pragma unroll
                    for (int kx = 0; kx < 4; kx++) {
                        int ix = ox - 1 + kx;
                        if ((unsigned)ix < 16u)
                            acc += xc[iy * 16 + ix] * wr[ky * 4 + kx];
                    }
                }
            }
        }
        out[b * 225 + threadIdx.x] = acc;
    }
}

// ---------------------------------------------------------------------------
extern "C" void kernel_launch(void* const* d_in, const int* in_sizes, int n_in,
                              void* d_out, int out_size) {
    const float* img  = (const float*)d_in[0];
    const int*   sidx = (const int*)  d_in[1];
    const float* w0 = (const float*)d_in[2];
    const float* b0 = (const float*)d_in[3];
    const float* w1 = (const float*)d_in[4];
    const float* w2 = (const float*)d_in[6];
    const float* wq = (const float*)d_in[8];
    const float* bq = (const float*)d_in[9];
    const float* wk = (const float*)d_in[10];
    const float* bk = (const float*)d_in[11];
    const float* wv = (const float*)d_in[12];
    const float* bv = (const float*)d_in[13];
    const float* gamma = (const float*)d_in[14];
    const float* wh = (const float*)d_in[15];
    const float* bh = (const float*)d_in[16];
    float* out = (float*)d_out;

    k_conv0   <<<B_ * 64, 256>>>(img, sidx, w0, b0);
    k_conv1g  <<<dim3(8, B_), 256>>>(sidx, w1);
    k_inorm1  <<<B_ * 128, 256>>>();
    k_qk      <<<dim3(4, 2, B_), 256>>>(sidx, wq, bq, wk, bk);
    k_vmma    <<<dim3(8, B_), 256>>>(sidx, wv, bv);
    k_attn_sm <<<B_ * 128, 256>>>();
    k_av      <<<dim3(16, B_), 256>>>(sidx, gamma);
    k_conv2g  <<<dim3(4, 4, B_), 256>>>(sidx, w2);
    k_inorm2  <<<B_ * 256, 256>>>();
    k_head    <<<B_, 256>>>(sidx, wh, bh, out);
}

// round 17
// speedup vs baseline: 2.6171x; 1.2570x over previous
#include <cuda_runtime.h>
#include <cuda_bf16.h>
#include <cstdint>

// ---------------------------------------------------------------------------
// MultiStageDiscriminator — tf32 mma for conv1/conv2/AV/V-proj; scalar rest.
// ---------------------------------------------------------------------------

#define B_ 16
#define SLOPE 0.2f

// ---- static scratch (zero-initialized; padded borders are never written) ----
__device__ float g_x0p[B_ * 64 * 66 * 66];     // conv0 out, padded 66x66
__device__ float g_t1 [B_ * 128 * 1024];       // conv1 raw (pre-norm)
__device__ float g_x1 [B_ * 128 * 1024];       // post inorm+leaky
__device__ float g_q  [B_ * 16 * 1024];
__device__ float g_k  [B_ * 16 * 1024];
__device__ float g_v  [B_ * 128 * 1024];
__device__ float g_attn[B_ * 1024 * 1024];     // 64 MB
__device__ float g_xap[B_ * 128 * 34 * 34];    // attn residual out, padded 34x34
__device__ float g_t2p[4 * B_ * 256 * 256];    // conv2 K-split partials
__device__ float g_x2 [B_ * 256 * 16 * 16];

__device__ __forceinline__ float lrelu(float v) { return v > 0.f ? v : SLOPE * v; }

__device__ __forceinline__ float tf32r(float x) {
    float r; asm("cvt.rna.tf32.f32 %0, %1;" : "=f"(r) : "f"(x)); return r;
}

__device__ __forceinline__ void mma_tf32(float d[4],
                                         uint32_t a0, uint32_t a1, uint32_t a2, uint32_t a3,
                                         uint32_t b0, uint32_t b1) {
    asm volatile(
        "mma.sync.aligned.m16n8k8.row.col.f32.tf32.tf32.f32 "
        "{%0,%1,%2,%3}, {%4,%5,%6,%7}, {%8,%9}, {%0,%1,%2,%3};\n"
        : "+f"(d[0]), "+f"(d[1]), "+f"(d[2]), "+f"(d[3])
        : "r"(a0), "r"(a1), "r"(a2), "r"(a3), "r"(b0), "r"(b1));
}

// ---------------------------------------------------------------------------
// K1: conv0 (1->64, k4 s2 p1, 128->64) + leaky -> padded 66x66.
// ---------------------------------------------------------------------------
__global__ void k_conv0(const float* __restrict__ img, const int* __restrict__ sidx,
                        const float* __restrict__ w0, const float* __restrict__ b0) {
    int b  = blockIdx.x >> 6;
    int oc = blockIdx.x & 63;
    int s  = sidx[b];
    __shared__ float ws[16];
    __shared__ float bias;
    if (threadIdx.x < 16) ws[threadIdx.x] = w0[(s * 64 + oc) * 16 + threadIdx.x];
    if (threadIdx.x == 0) bias = b0[s * 64 + oc];
    __syncthreads();
    const float* im  = img + b * 128 * 128;
    float*       out = g_x0p + (b * 64 + oc) * 4356;
    for (int p = threadIdx.x; p < 4096; p += blockDim.x) {
        int oy = p >> 6, ox = p & 63;
        float acc = bias;
        #pragma unroll
        for (int ky = 0; ky < 4; ky++) {
            int iy = 2 * oy - 1 + ky;
            if ((unsigned)iy < 128u) {
                #pragma unroll
                for (int kx = 0; kx < 4; kx++) {
                    int ix = 2 * ox - 1 + kx;
                    if ((unsigned)ix < 128u)
                        acc += im[iy * 128 + ix] * ws[ky * 4 + kx];
                }
            }
        }
        out[(oy + 1) * 66 + ox + 1] = lrelu(acc);
    }
}

// ---------------------------------------------------------------------------
// K2: conv1 as tf32 implicit GEMM.
// ---------------------------------------------------------------------------
__global__ void __launch_bounds__(256, 2)
k_conv1g(const int* __restrict__ sidx, const float* __restrict__ w1) {
    int b  = blockIdx.y;
    int n0 = blockIdx.x * 128;
    int s  = sidx[b];
    __shared__ __align__(16) float As[128][36];
    __shared__ __align__(16) float Bs[32][136];

    int tid  = threadIdx.x;
    int wid  = tid >> 5, lane = tid & 31;
    int warp_m = wid >> 2;
    int warp_n = wid & 3;
    int cw = warp_m * 64;
    int nw = warp_n * 32;
    int gr = lane >> 2, tg = lane & 3;

    float acc[4][4][4] = {};

    int nn = tid & 127, kh = tid >> 7;
    int n  = n0 + nn;
    int oy = n >> 5, ox = n & 31;
    const float* wbase = w1 + (size_t)(s * 128) * 1024;
    int a_oc = tid >> 1, a_k0 = (tid & 1) * 16;

    for (int m0 = 0; m0 < 1024; m0 += 32) {
        {
            const float* wr = wbase + a_oc * 1024 + m0 + a_k0;
            #pragma unroll
            for (int i = 0; i < 16; i++) As[a_oc][a_k0 + i] = tf32r(wr[i]);
        }
        {
            int ic = (m0 >> 4) + kh;
            const float* src = g_x0p + ((b * 64 + ic) * 4356) + (2 * oy) * 66 + 2 * ox;
            #pragma unroll
            for (int ky = 0; ky < 4; ky++)
                #pragma unroll
                for (int kx = 0; kx < 4; kx++)
                    Bs[kh * 16 + ky * 4 + kx][nn] = tf32r(src[ky * 66 + kx]);
        }
        __syncthreads();
        #pragma unroll
        for (int k8 = 0; k8 < 32; k8 += 8) {
            uint32_t a[4][4];
            #pragma unroll
            for (int mi = 0; mi < 4; mi++) {
                a[mi][0] = __float_as_uint(As[cw + mi * 16 + gr    ][k8 + tg    ]);
                a[mi][1] = __float_as_uint(As[cw + mi * 16 + gr + 8][k8 + tg    ]);
                a[mi][2] = __float_as_uint(As[cw + mi * 16 + gr    ][k8 + tg + 4]);
                a[mi][3] = __float_as_uint(As[cw + mi * 16 + gr + 8][k8 + tg + 4]);
            }
            uint32_t bf[4][2];
            #pragma unroll
            for (int nj = 0; nj < 4; nj++) {
                bf[nj][0] = __float_as_uint(Bs[k8 + tg    ][nw + nj * 8 + gr]);
                bf[nj][1] = __float_as_uint(Bs[k8 + tg + 4][nw + nj * 8 + gr]);
            }
            #pragma unroll
            for (int mi = 0; mi < 4; mi++)
                #pragma unroll
                for (int nj = 0; nj < 4; nj++)
                    mma_tf32(acc[mi][nj], a[mi][0], a[mi][1], a[mi][2], a[mi][3],
                             bf[nj][0], bf[nj][1]);
        }
        __syncthreads();
    }

    float* O = g_t1 + b * 128 * 1024;
    #pragma unroll
    for (int mi = 0; mi < 4; mi++) {
        int c_lo = cw + mi * 16 + gr;
        int c_hi = c_lo + 8;
        #pragma unroll
        for (int nj = 0; nj < 4; nj++) {
            int nc = n0 + nw + nj * 8 + tg * 2;
            O[c_lo * 1024 + nc]     = acc[mi][nj][0];
            O[c_lo * 1024 + nc + 1] = acc[mi][nj][1];
            O[c_hi * 1024 + nc]     = acc[mi][nj][2];
            O[c_hi * 1024 + nc + 1] = acc[mi][nj][3];
        }
    }
}

// ---------------------------------------------------------------------------
// Instance norm + leaky helper (block per (b,c)).
// ---------------------------------------------------------------------------
__device__ __forceinline__ void inorm_block(const float* x, float* y, int N) {
    float s = 0.f, s2 = 0.f;
    for (int i = threadIdx.x; i < N; i += blockDim.x) {
        float v = x[i]; s += v; s2 += v * v;
    }
    __shared__ float rs[8], rs2[8];
    #pragma unroll
    for (int o = 16; o; o >>= 1) {
        s  += __shfl_down_sync(~0u, s, o);
        s2 += __shfl_down_sync(~0u, s2, o);
    }
    int w = threadIdx.x >> 5, l = threadIdx.x & 31;
    if (l == 0) { rs[w] = s; rs2[w] = s2; }
    __syncthreads();
    if (w == 0) {
        s  = (l < (int)(blockDim.x >> 5)) ? rs[l]  : 0.f;
        s2 = (l < (int)(blockDim.x >> 5)) ? rs2[l] : 0.f;
        #pragma unroll
        for (int o = 4; o; o >>= 1) {
            s  += __shfl_down_sync(~0u, s, o);
            s2 += __shfl_down_sync(~0u, s2, o);
        }
        if (l == 0) {
            float m   = s / (float)N;
            float var = s2 / (float)N - m * m;
            rs[0]  = m;
            rs2[0] = rsqrtf(var + 1e-5f);
        }
    }
    __syncthreads();
    float m = rs[0], inv = rs2[0];
    for (int i = threadIdx.x; i < N; i += blockDim.x)
        y[i] = lrelu((x[i] - m) * inv);
}

__global__ void k_inorm1() {
    int bc = blockIdx.x;
    inorm_block(g_t1 + bc * 1024, g_x1 + bc * 1024, 1024);
}

// ---------------------------------------------------------------------------
// K3a: q/k 1x1 convs (scalar). grid = (8 n-tiles, 2, B), block 128 -> 256 CTAs.
// ---------------------------------------------------------------------------
__global__ void k_qk(const int* __restrict__ sidx,
                     const float* __restrict__ wq, const float* __restrict__ bq,
                     const float* __restrict__ wk, const float* __restrict__ bk) {
    int b = blockIdx.z;
    int g = blockIdx.y;
    int s = sidx[b];
    const float *W, *Bp;
    float* out;
    if (g == 0) { W = wq + s * 16 * 128; Bp = bq + s * 16; out = g_q + b * 16 * 1024; }
    else        { W = wk + s * 16 * 128; Bp = bk + s * 16; out = g_k + b * 16 * 1024; }
    __shared__ __align__(16) float ws[128 * 16];   // [c][ch]
    __shared__ float bsm[16];
    for (int i = threadIdx.x; i < 2048; i += blockDim.x) {
        int ch = i & 15, c = i >> 4;
        ws[i] = W[ch * 128 + c];
    }
    if (threadIdx.x < 16) bsm[threadIdx.x] = Bp[threadIdx.x];
    __syncthreads();

    const float* x = g_x1 + b * 128 * 1024;
    int n = blockIdx.x * 128 + threadIdx.x;
    float acc[16];
    #pragma unroll
    for (int j = 0; j < 16; j++) acc[j] = bsm[j];
    for (int c = 0; c < 128; c++) {
        float v = x[c * 1024 + n];
        const float* wr = ws + c * 16;
        #pragma unroll
        for (int j = 0; j < 16; j += 4) {
            float4 w4 = *(const float4*)(wr + j);
            acc[j]     += v * w4.x; acc[j + 1] += v * w4.y;
            acc[j + 2] += v * w4.z; acc[j + 3] += v * w4.w;
        }
    }
    #pragma unroll
    for (int j = 0; j < 16; j++) out[j * 1024 + n] = acc[j];
}

// ---------------------------------------------------------------------------
// K3b: V projection as tf32 GEMM.
// ---------------------------------------------------------------------------
__global__ void __launch_bounds__(256, 2)
k_vmma(const int* __restrict__ sidx,
       const float* __restrict__ wv, const float* __restrict__ bv) {
    int b  = blockIdx.y;
    int n0 = blockIdx.x * 128;
    int s  = sidx[b];
    __shared__ __align__(16) float As[128][36];
    __shared__ __align__(16) float Bs[32][136];

    int tid  = threadIdx.x;
    int wid  = tid >> 5, lane = tid & 31;
    int warp_m = wid >> 2;
    int warp_n = wid & 3;
    int cw = warp_m * 64;
    int nw = warp_n * 32;
    int gr = lane >> 2, tg = lane & 3;

    float acc[4][4][4] = {};

    const float* wbase = wv + (size_t)(s * 128) * 128;
    const float* x     = g_x1 + b * 128 * 1024;
    int a_ch = tid >> 1, a_k0 = (tid & 1) * 16;

    for (int c0 = 0; c0 < 128; c0 += 32) {
        {
            const float* wr = wbase + a_ch * 128 + c0 + a_k0;
            #pragma unroll
            for (int i = 0; i < 16; i++) As[a_ch][a_k0 + i] = tf32r(wr[i]);
        }
        #pragma unroll
        for (int r = 0; r < 16; r++) {
            int idx = tid + r * 256;
            int c = idx >> 7, nn = idx & 127;
            Bs[c][nn] = tf32r(x[(c0 + c) * 1024 + n0 + nn]);
        }
        __syncthreads();
        #pragma unroll
        for (int k8 = 0; k8 < 32; k8 += 8) {
            uint32_t a[4][4];
            #pragma unroll
            for (int mi = 0; mi < 4; mi++) {
                a[mi][0] = __float_as_uint(As[cw + mi * 16 + gr    ][k8 + tg    ]);
                a[mi][1] = __float_as_uint(As[cw + mi * 16 + gr + 8][k8 + tg    ]);
                a[mi][2] = __float_as_uint(As[cw + mi * 16 + gr    ][k8 + tg + 4]);
                a[mi][3] = __float_as_uint(As[cw + mi * 16 + gr + 8][k8 + tg + 4]);
            }
            uint32_t bf[4][2];
            #pragma unroll
            for (int nj = 0; nj < 4; nj++) {
                bf[nj][0] = __float_as_uint(Bs[k8 + tg    ][nw + nj * 8 + gr]);
                bf[nj][1] = __float_as_uint(Bs[k8 + tg + 4][nw + nj * 8 + gr]);
            }
            #pragma unroll
            for (int mi = 0; mi < 4; mi++)
                #pragma unroll
                for (int nj = 0; nj < 4; nj++)
                    mma_tf32(acc[mi][nj], a[mi][0], a[mi][1], a[mi][2], a[mi][3],
                             bf[nj][0], bf[nj][1]);
        }
        __syncthreads();
    }

    const float* bvp = bv + s * 128;
    float* O = g_v + b * 128 * 1024;
    #pragma unroll
    for (int mi = 0; mi < 4; mi++) {
        int c_lo = cw + mi * 16 + gr;
        int c_hi = c_lo + 8;
        float bl = bvp[c_lo], bh = bvp[c_hi];
        #pragma unroll
        for (int nj = 0; nj < 4; nj++) {
            int nc = n0 + nw + nj * 8 + tg * 2;
            O[c_lo * 1024 + nc]     = acc[mi][nj][0] + bl;
            O[c_lo * 1024 + nc + 1] = acc[mi][nj][1] + bl;
            O[c_hi * 1024 + nc]     = acc[mi][nj][2] + bh;
            O[c_hi * 1024 + nc + 1] = acc[mi][nj][3] + bh;
        }
    }
}

// ---------------------------------------------------------------------------
// K4: energies + row softmax (unroll-2 form).
// ---------------------------------------------------------------------------
__global__ void k_attn_sm() {
    int b  = blockIdx.x >> 7;
    int n0 = (blockIdx.x & 127) * 8;
    __shared__ float qs[8 * 16];
    __shared__ float es[8 * 1024];   // 32KB
    if (threadIdx.x < 128) {
        int n = threadIdx.x >> 4, i = threadIdx.x & 15;
        qs[n * 16 + i] = g_q[(b * 16 + i) * 1024 + n0 + n];
    }
    __syncthreads();
    const float* kp = g_k + b * 16 * 1024;
    #pragma unroll 2
    for (int m = threadIdx.x; m < 1024; m += 256) {
        float kv[16];
        #pragma unroll
        for (int i = 0; i < 16; i++) kv[i] = kp[i * 1024 + m];
        #pragma unroll
        for (int n = 0; n < 8; n++) {
            float e = 0.f;
            #pragma unroll
            for (int i = 0; i < 16; i++) e += qs[n * 16 + i] * kv[i];
            es[n * 1024 + m] = e;
        }
    }
    __syncthreads();
    int w = threadIdx.x >> 5, l = threadIdx.x & 31;
    float mx = -1e30f;
    for (int m = l; m < 1024; m += 32) mx = fmaxf(mx, es[w * 1024 + m]);
    #pragma unroll
    for (int o = 16; o; o >>= 1) mx = fmaxf(mx, __shfl_xor_sync(~0u, mx, o));
    float sum = 0.f;
    for (int m = l; m < 1024; m += 32) {
        float p = __expf(es[w * 1024 + m] - mx);
        es[w * 1024 + m] = p;
        sum += p;
    }
    #pragma unroll
    for (int o = 16; o; o >>= 1) sum += __shfl_xor_sync(~0u, sum, o);
    float r = 1.f / sum;
    float* out = g_attn + ((size_t)b * 1024 + n0 + w) * 1024;
    for (int m = l; m < 1024; m += 32) out[m] = es[w * 1024 + m] * r;
}

// ---------------------------------------------------------------------------
// K5: xa = gamma * (V @ attn^T) + x1 -> PADDED 34x34.   [tf32 mma.sync]
// ---------------------------------------------------------------------------
__global__ void __launch_bounds__(256, 2)
k_av(const int* __restrict__ sidx, const float* __restrict__ gamma) {
    int b  = blockIdx.y;
    int n0 = blockIdx.x * 64;
    float gm = gamma[sidx[b]];
    const float* V = g_v + b * 128 * 1024;
    const float* P = g_attn + (size_t)b * 1024 * 1024;

    __shared__ __align__(16) float As[128][36];
    __shared__ __align__(16) float Bs[64][36];

    int tid  = threadIdx.x;
    int wid  = tid >> 5, lane = tid & 31;
    int warp_m = wid & 3;
    int warp_n = wid >> 2;
    int cw = warp_m * 32;
    int nw = warp_n * 32;
    int gr = lane >> 2;
    int tg = lane & 3;

    float acc[2][4][4] = {};

    for (int m0 = 0; m0 < 1024; m0 += 32) {
        #pragma unroll
        for (int r = 0; r < 4; r++) {
            int idx = tid + r * 256;
            int c   = idx >> 3;
            int k4  = (idx & 7) * 4;
            float4 v = *(const float4*)&V[c * 1024 + m0 + k4];
            As[c][k4 + 0] = tf32r(v.x);
            As[c][k4 + 1] = tf32r(v.y);
            As[c][k4 + 2] = tf32r(v.z);
            As[c][k4 + 3] = tf32r(v.w);
        }
        #pragma unroll
        for (int r = 0; r < 2; r++) {
            int idx = tid + r * 256;
            int n   = idx >> 3;
            int k4  = (idx & 7) * 4;
            float4 v = *(const float4*)&P[(size_t)(n0 + n) * 1024 + m0 + k4];
            Bs[n][k4 + 0] = tf32r(v.x);
            Bs[n][k4 + 1] = tf32r(v.y);
            Bs[n][k4 + 2] = tf32r(v.z);
            Bs[n][k4 + 3] = tf32r(v.w);
        }
        __syncthreads();

        #pragma unroll
        for (int k8 = 0; k8 < 32; k8 += 8) {
            uint32_t a[2][4];
            #pragma unroll
            for (int mi = 0; mi < 2; mi++) {
                a[mi][0] = __float_as_uint(As[cw + mi * 16 + gr    ][k8 + tg    ]);
                a[mi][1] = __float_as_uint(As[cw + mi * 16 + gr + 8][k8 + tg    ]);
                a[mi][2] = __float_as_uint(As[cw + mi * 16 + gr    ][k8 + tg + 4]);
                a[mi][3] = __float_as_uint(As[cw + mi * 16 + gr + 8][k8 + tg + 4]);
            }
            uint32_t bf[4][2];
            #pragma unroll
            for (int nj = 0; nj < 4; nj++) {
                bf[nj][0] = __float_as_uint(Bs[nw + nj * 8 + gr][k8 + tg    ]);
                bf[nj][1] = __float_as_uint(Bs[nw + nj * 8 + gr][k8 + tg + 4]);
            }
            #pragma unroll
            for (int mi = 0; mi < 2; mi++)
                #pragma unroll
                for (int nj = 0; nj < 4; nj++)
                    mma_tf32(acc[mi][nj], a[mi][0], a[mi][1], a[mi][2], a[mi][3],
                             bf[nj][0], bf[nj][1]);
        }
        __syncthreads();
    }

    const float* X = g_x1 + b * 128 * 1024;
    float*       O = g_xap + b * 128 * 1156;
    #pragma unroll
    for (int mi = 0; mi < 2; mi++) {
        int c_lo = cw + mi * 16 + gr;
        int c_hi = c_lo + 8;
        #pragma unroll
        for (int nj = 0; nj < 4; nj++) {
            int n = n0 + nw + nj * 8 + tg * 2;
            int y = n >> 5, x = n & 31;
            int po = (y + 1) * 34 + x + 1;
            O[c_lo * 1156 + po]     = gm * acc[mi][nj][0] + X[c_lo * 1024 + n];
            O[c_lo * 1156 + po + 1] = gm * acc[mi][nj][1] + X[c_lo * 1024 + n + 1];
            O[c_hi * 1156 + po]     = gm * acc[mi][nj][2] + X[c_hi * 1024 + n];
            O[c_hi * 1156 + po + 1] = gm * acc[mi][nj][3] + X[c_hi * 1024 + n + 1];
        }
    }
}

// ---------------------------------------------------------------------------
// K6: conv2 as tf32 implicit GEMM with split-K.
// ---------------------------------------------------------------------------
__global__ void __launch_bounds__(256, 2)
k_conv2g(const int* __restrict__ sidx, const float* __restrict__ w2) {
    int ks = blockIdx.x;
    int mt = blockIdx.y >> 1;
    int nt = blockIdx.y & 1;
    int b  = blockIdx.z;
    int s  = sidx[b];
    __shared__ __align__(16) float As[128][20];
    __shared__ __align__(16) float Bs[16][136];

    int tid  = threadIdx.x;
    int wid  = tid >> 5, lane = tid & 31;
    int warp_m = wid >> 2;
    int warp_n = wid & 3;
    int cw = warp_m * 64;
    int nw = warp_n * 32;
    int gr = lane >> 2, tg = lane & 3;

    float acc[4][4][4] = {};

    int nn = tid & 127, half = tid >> 7;
    int n  = nt * 128 + nn;
    int oy = n >> 4, ox = n & 15;
    const float* wbase = w2 + (size_t)(s * 256 + mt * 128) * 2048 + ks * 512;
    int a_oc = tid >> 1, a_k0 = (tid & 1) * 8;

    for (int cc = 0; cc < 32; cc++) {
        int ic = ks * 32 + cc;
        {
            const float* wr = wbase + a_oc * 2048 + cc * 16 + a_k0;
            #pragma unroll
            for (int i = 0; i < 8; i++) As[a_oc][a_k0 + i] = tf32r(wr[i]);
        }
        {
            const float* src = g_xap + ((b * 128 + ic) * 1156) + (2 * oy) * 34 + 2 * ox;
            #pragma unroll
            for (int dy = 0; dy < 2; dy++)
                #pragma unroll
                for (int kx = 0; kx < 4; kx++)
                    Bs[half * 8 + dy * 4 + kx][nn] =
                        tf32r(src[(half * 2 + dy) * 34 + kx]);
        }
        __syncthreads();
        #pragma unroll
        for (int k8 = 0; k8 < 16; k8 += 8) {
            uint32_t a[4][4];
            #pragma unroll
            for (int mi = 0; mi < 4; mi++) {
                a[mi][0] = __float_as_uint(As[cw + mi * 16 + gr    ][k8 + tg    ]);
                a[mi][1] = __float_as_uint(As[cw + mi * 16 + gr + 8][k8 + tg    ]);
                a[mi][2] = __float_as_uint(As[cw + mi * 16 + gr    ][k8 + tg + 4]);
                a[mi][3] = __float_as_uint(As[cw + mi * 16 + gr + 8][k8 + tg + 4]);
            }
            uint32_t bf[4][2];
            #pragma unroll
            for (int nj = 0; nj < 4; nj++) {
                bf[nj][0] = __float_as_uint(Bs[k8 + tg    ][nw + nj * 8 + gr]);
                bf[nj][1] = __float_as_uint(Bs[k8 + tg + 4][nw + nj * 8 + gr]);
            }
            #pragma unroll
            for (int mi = 0; mi < 4; mi++)
                #pragma unroll
                for (int nj = 0; nj < 4; nj++)
                    mma_tf32(acc[mi][nj], a[mi][0], a[mi][1], a[mi][2], a[mi][3],
                             bf[nj][0], bf[nj][1]);
        }
        __syncthreads();
    }

    float* O = g_t2p + ((size_t)(ks * B_ + b) * 256 + mt * 128) * 256;
    #pragma unroll
    for (int mi = 0; mi < 4; mi++) {
        int c_lo = cw + mi * 16 + gr;
        int c_hi = c_lo + 8;
        #pragma unroll
        for (int nj = 0; nj < 4; nj++) {
            int nc = nt * 128 + nw + nj * 8 + tg * 2;
            O[c_lo * 256 + nc]     = acc[mi][nj][0];
            O[c_lo * 256 + nc + 1] = acc[mi][nj][1];
            O[c_hi * 256 + nc]     = acc[mi][nj][2];
            O[c_hi * 256 + nc + 1] = acc[mi][nj][3];
        }
    }
}

// ---------------------------------------------------------------------------
// K6b: sum 4 K-split partials + instance norm + leaky -> g_x2.
// ---------------------------------------------------------------------------
__global__ void k_inorm2() {
    int b = blockIdx.x >> 8;
    int c = blockIdx.x & 255;
    int t = threadIdx.x;
    float v = 0.f;
    #pragma unroll
    for (int ks = 0; ks < 4; ks++)
        v += g_t2p[((size_t)(ks * B_ + b) * 256 + c) * 256 + t];

    float sv = v, qv = v * v;
    __shared__ float rs[8], rs2[8];
    #pragma unroll
    for (int o = 16; o; o >>= 1) {
        sv += __shfl_down_sync(~0u, sv, o);
        qv += __shfl_down_sync(~0u, qv, o);
    }
    int w = t >> 5, l = t & 31;
    if (l == 0) { rs[w] = sv; rs2[w] = qv; }
    __syncthreads();
    if (w == 0) {
        sv = (l < 8) ? rs[l]  : 0.f;
        qv = (l < 8) ? rs2[l] : 0.f;
        #pragma unroll
        for (int o = 4; o; o >>= 1) {
            sv += __shfl_down_sync(~0u, sv, o);
            qv += __shfl_down_sync(~0u, qv, o);
        }
        if (l == 0) {
            float m   = sv * (1.f / 256.f);
            float var = qv * (1.f / 256.f) - m * m;
            rs[0]  = m;
            rs2[0] = rsqrtf(var + 1e-5f);
        }
    }
    __syncthreads();
    g_x2[(b * 256 + c) * 256 + t] = lrelu((v - rs[0]) * rs2[0]);
}

// ---------------------------------------------------------------------------
// K7: head conv (256->1, k4 s1 p1, 16->15), parallelized.
// grid = (15 rows, B) = 240 CTAs, block = 256 (240 active).
// ---------------------------------------------------------------------------
__global__ void k_head(const int* __restrict__ sidx,
                       const float* __restrict__ wh, const float* __restrict__ bh,
                       float* __restrict__ out) {
    int oy = blockIdx.x;     // 0..14
    int b  = blockIdx.y;
    int s  = sidx[b];
    __shared__ float ws[256 * 16];   // 16KB
    for (int i = threadIdx.x; i < 4096; i += blockDim.x) ws[i] = wh[s * 4096 + i];
    __shared__ float red[16][16];    // [icg][ox]
    __syncthreads();

    int t = threadIdx.x;
    if (t < 240) {
        int ox  = t % 15;
        int icg = t / 15;            // 0..15
        float acc = 0.f;
        const float* x = g_x2 + b * 256 * 256;
        for (int ic = icg * 16; ic < icg * 16 + 16; ic++) {
            const float* xc = x + ic * 256;
            const float* wr = ws + ic * 16;
            #pragma unroll
            for (int ky = 0; ky < 4; ky++) {
                int iy = oy - 1 + ky;
                if ((unsigned)iy < 16u) {
                    #pragma unroll
                    for (int kx = 0; kx < 4; kx++) {
                        int ix = ox - 1 + kx;
                        if ((unsigned)ix < 16u)
                            acc += xc[iy * 16 + ix] * wr[ky * 4 + kx];
                    }
                }
            }
        }
        red[icg][ox] = acc;
    }
    __syncthreads();
    if (t < 15) {
        float acc = bh[s];
        #pragma unroll
        for (int icg = 0; icg < 16; icg++) acc += red[icg][t];
        out[b * 225 + oy * 15 + t] = acc;
    }
}

// ---------------------------------------------------------------------------
extern "C" void kernel_launch(void* const* d_in, const int* in_sizes, int n_in,
                              void* d_out, int out_size) {
    const float* img  = (const float*)d_in[0];
    const int*   sidx = (const int*)  d_in[1];
    const float* w0 = (const float*)d_in[2];
    const float* b0 = (const float*)d_in[3];
    const float* w1 = (const float*)d_in[4];
    const float* w2 = (const float*)d_in[6];
    const float* wq = (const float*)d_in[8];
    const float* bq = (const float*)d_in[9];
    const float* wk = (const float*)d_in[10];
    const float* bk = (const float*)d_in[11];
    const float* wv = (const float*)d_in[12];
    const float* bv = (const float*)d_in[13];
    const float* gamma = (const float*)d_in[14];
    const float* wh = (const float*)d_in[15];
    const float* bh = (const float*)d_in[16];
    float* out = (float*)d_out;

    k_conv0   <<<B_ * 64, 256>>>(img, sidx, w0, b0);
    k_conv1g  <<<dim3(8, B_), 256>>>(sidx, w1);
    k_inorm1  <<<B_ * 128, 256>>>();
    k_qk      <<<dim3(8, 2, B_), 128>>>(sidx, wq, bq, wk, bk);
    k_vmma    <<<dim3(8, B_), 256>>>(sidx, wv, bv);
    k_attn_sm <<<B_ * 128, 256>>>();
    k_av      <<<dim3(16, B_), 256>>>(sidx, gamma);
    k_conv2g  <<<dim3(4, 4, B_), 256>>>(sidx, w2);
    k_inorm2  <<<B_ * 256, 256>>>();
    k_head    <<<dim3(15, B_), 256>>>(sidx, wh, bh, out);
}